// round 14
// baseline (speedup 1.0000x reference)
#include <cuda_runtime.h>
#include <cuda_fp16.h>

#define NN 100000
#define NE 3200000
#define NG 256
#define NB_SCAN 196   // ceil(NN/512)

// ---------------- static scratch ----------------
__device__ int    g_deg[NN];
__device__ int    g_rowptr[NN + 1];      // rows padded to multiple of 4 edges
__device__ int    g_bsum[NB_SCAN];
__device__ int4   g_rank4[NE / 4];       // per-edge rank within its row
__device__ int2   g_csrcv[NE + 3 * NN];  // (col, val as half2(v,v)) CSR
__device__ uint4  g_xpack[NN];           // x packed: 5 x fp16 + pad (16B/node)
__device__ uint2  g_x1f8[NN * 8];        // x1 fp8 e4m3 [NN,64]
__device__ uint2  g_x2f8[NN * 8];        // x2 fp8 e4m3 [NN,64]
__device__ float  g_pool[NG * 64];

// ---------------- f32x2 helpers ----------------
static __forceinline__ __device__ unsigned long long pk2(float lo, float hi) {
    unsigned long long r;
    asm("mov.b64 %0,{%1,%2};" : "=l"(r) : "f"(lo), "f"(hi));
    return r;
}
static __forceinline__ __device__ unsigned long long fma2(unsigned long long a,
                                                          unsigned long long b,
                                                          unsigned long long c) {
    unsigned long long d;
    asm("fma.rn.f32x2 %0,%1,%2,%3;" : "=l"(d) : "l"(a), "l"(b), "l"(c));
    return d;
}
static __forceinline__ __device__ void upk2(unsigned long long v, float& lo, float& hi) {
    asm("mov.b64 {%0,%1},%2;" : "=f"(lo), "=f"(hi) : "l"(v));
}

// ---------------- fp8 helpers ----------------
static __forceinline__ __device__ __half2 e4m3x2_to_h2(unsigned short u) {
    unsigned int r;
    asm("cvt.rn.f16x2.e4m3x2 %0, %1;" : "=r"(r) : "h"(u));
    return *(__half2*)&r;
}
static __forceinline__ __device__ unsigned short f2_to_e4m3x2(float hi, float lo) {
    unsigned short r;
    asm("cvt.rn.satfinite.e4m3x2.f32 %0, %1, %2;" : "=h"(r) : "f"(hi), "f"(lo));
    return r;
}

// edge-accumulate macros (VB = half2(v,v) bits)
#define L1_EDGEV(XA, VB) { \
    unsigned vb_ = (unsigned)(VB); \
    float v = __half2float(*(__half*)&vb_); \
    float2 p01 = __half22float2(*(__half2*)&XA.x); \
    float2 p23 = __half22float2(*(__half2*)&XA.y); \
    float2 p4x = __half22float2(*(__half2*)&XA.z); \
    a0 += v * p01.x; a1 += v * p01.y; a2 += v * p23.x; \
    a3 += v * p23.y; a4 += v * p4x.x; }

#define F8_EDGEV(AA, VB) { \
    unsigned vb_ = (unsigned)(VB); \
    __half2 v2 = *(__half2*)&vb_; \
    acc[0] = __hfma2(v2, e4m3x2_to_h2((unsigned short)(AA.x & 0xffff)), acc[0]); \
    acc[1] = __hfma2(v2, e4m3x2_to_h2((unsigned short)(AA.x >> 16)), acc[1]); \
    acc[2] = __hfma2(v2, e4m3x2_to_h2((unsigned short)(AA.y & 0xffff)), acc[2]); \
    acc[3] = __hfma2(v2, e4m3x2_to_h2((unsigned short)(AA.y >> 16)), acc[3]); \
    acc[4] = __hfma2(v2, e4m3x2_to_h2((unsigned short)(AA.z & 0xffff)), acc[4]); \
    acc[5] = __hfma2(v2, e4m3x2_to_h2((unsigned short)(AA.z >> 16)), acc[5]); \
    acc[6] = __hfma2(v2, e4m3x2_to_h2((unsigned short)(AA.w & 0xffff)), acc[6]); \
    acc[7] = __hfma2(v2, e4m3x2_to_h2((unsigned short)(AA.w >> 16)), acc[7]); }

// ---------------- zero + pack x ----------------
__global__ void zero_pack_kernel(const float* __restrict__ x) {
    int i = blockIdx.x * blockDim.x + threadIdx.x;
    if (i < NN) {
        g_deg[i] = 0;
        const float* xr = x + (long)i * 5;
        uint4 u;
        *(__half2*)&u.x = __floats2half2_rn(xr[0], xr[1]);
        *(__half2*)&u.y = __floats2half2_rn(xr[2], xr[3]);
        *(__half2*)&u.z = __floats2half2_rn(xr[4], 0.f);
        u.w = 0;
        g_xpack[i] = u;
    }
    if (i < NG * 64) g_pool[i] = 0.f;
}

// ---------------- CSR build ----------------
__global__ void hist_kernel(const int4* __restrict__ rows4) {
    int i = blockIdx.x * blockDim.x + threadIdx.x;
    if (i < NE / 4) {
        int4 r = rows4[i];
        int4 k;
        k.x = atomicAdd(&g_deg[r.x], 1);
        k.y = atomicAdd(&g_deg[r.y], 1);
        k.z = atomicAdd(&g_deg[r.z], 1);
        k.w = atomicAdd(&g_deg[r.w], 1);
        g_rank4[i] = k;
    }
}

__global__ void scanA_kernel() {
    __shared__ int s[512];
    int t = threadIdx.x;
    int i = blockIdx.x * 512 + t;
    s[t] = (i < NN) ? ((g_deg[i] + 3) & ~3) : 0;   // pad to multiple of 4
    __syncthreads();
    for (int off = 256; off > 0; off >>= 1) {
        if (t < off) s[t] += s[t + off];
        __syncthreads();
    }
    if (t == 0) g_bsum[blockIdx.x] = s[0];
}

// per-block base + in-block scan over PADDED degrees -> rowptr; zero pad slots
__global__ void scanC_kernel() {
    __shared__ int rs[512];
    __shared__ int s[512];
    __shared__ int sbase;
    int t = threadIdx.x;
    int bid = blockIdx.x;
    int part = (t < bid) ? g_bsum[t] : 0;
    rs[t] = part;
    __syncthreads();
    for (int off = 256; off > 0; off >>= 1) {
        if (t < off) rs[t] += rs[t + off];
        __syncthreads();
    }
    if (t == 0) sbase = rs[0];
    int i = bid * 512 + t;
    int d = (i < NN) ? g_deg[i] : 0;
    int dp = (d + 3) & ~3;
    s[t] = dp;
    __syncthreads();
    for (int off = 1; off < 512; off <<= 1) {
        int v = 0;
        if (t >= off) v = s[t - off];
        __syncthreads();
        if (t >= off) s[t] += v;
        __syncthreads();
    }
    int incl = s[t];
    if (i < NN) {
        int p = sbase + incl - dp;
        g_rowptr[i] = p;
        for (int j = d; j < dp; j++) g_csrcv[p + j] = make_int2(0, 0);  // zero pads
        if (i == NN - 1) g_rowptr[NN] = sbase + incl;
    }
}

// rank-based scatter; val stored pre-packed as half2(v,v)
__global__ void scatter_kernel(const int4* __restrict__ rows4,
                               const int4* __restrict__ cols4,
                               const float4* __restrict__ vals4) {
    int i = blockIdx.x * blockDim.x + threadIdx.x;
    if (i < NE / 4) {
        int4 r = rows4[i];
        int4 c = cols4[i];
        float4 v = vals4[i];
        int4 k = g_rank4[i];
        int p0 = __ldg(&g_rowptr[r.x]) + k.x;
        int p1 = __ldg(&g_rowptr[r.y]) + k.y;
        int p2 = __ldg(&g_rowptr[r.z]) + k.z;
        int p3 = __ldg(&g_rowptr[r.w]) + k.w;
        __half2 h0 = __float2half2_rn(v.x);
        __half2 h1 = __float2half2_rn(v.y);
        __half2 h2 = __float2half2_rn(v.z);
        __half2 h3 = __float2half2_rn(v.w);
        g_csrcv[p0] = make_int2(c.x, *(int*)&h0);
        g_csrcv[p1] = make_int2(c.y, *(int*)&h1);
        g_csrcv[p2] = make_int2(c.z, *(int*)&h2);
        g_csrcv[p3] = make_int2(c.w, *(int*)&h3);
    }
}

// ---------------- layer 1: row-per-thread spmm(x), pipelined 2-pair loop --------
__global__ void __launch_bounds__(128)
spmm_l1_kernel(const float* __restrict__ W1, const float* __restrict__ b1,
               const int* __restrict__ batch) {
    __shared__ float  W1s[320];
    __shared__ float  bs[64];
    __shared__ __half sp_h[128 * 72];   // fp16 staging, padded stride 72
    __shared__ int    sb[128];
    int tid = threadIdx.x;
    for (int i = tid; i < 320; i += 128) W1s[i] = W1[i];
    if (tid < 64) bs[tid] = b1[tid];
    int base = blockIdx.x * 128;
    {
        int nd = base + tid;
        sb[tid] = batch[nd < NN ? nd : (NN - 1)];
    }
    __syncthreads();
    int row = base + tid;
    float a0 = 0, a1 = 0, a2 = 0, a3 = 0, a4 = 0;
    if (row < NN) {
        const int4* csr4 = (const int4*)g_csrcv;
        int start = g_rowptr[row];
        int npairs = (g_rowptr[row + 1] - start) >> 1;   // even (pad to 4 edges)
        int p2 = start >> 1;
        if (npairs > 0) {
            int4 cvA = __ldcs(&csr4[p2]);
            int4 cvB = __ldcs(&csr4[p2 + 1]);
            while (npairs > 2) {
                int4 cvC = __ldcs(&csr4[p2 + 2]);
                int4 cvD = __ldcs(&csr4[p2 + 3]);
                uint4 x0 = g_xpack[cvA.x];
                uint4 x1 = g_xpack[cvA.z];
                uint4 x2 = g_xpack[cvB.x];
                uint4 x3 = g_xpack[cvB.z];
                L1_EDGEV(x0, cvA.y)
                L1_EDGEV(x1, cvA.w)
                L1_EDGEV(x2, cvB.y)
                L1_EDGEV(x3, cvB.w)
                cvA = cvC; cvB = cvD;
                p2 += 2; npairs -= 2;
            }
            uint4 x0 = g_xpack[cvA.x];
            uint4 x1 = g_xpack[cvA.z];
            uint4 x2 = g_xpack[cvB.x];
            uint4 x3 = g_xpack[cvB.z];
            L1_EDGEV(x0, cvA.y)
            L1_EDGEV(x1, cvA.w)
            L1_EDGEV(x2, cvB.y)
            L1_EDGEV(x3, cvB.w)
        }
    }
    // epilogue: out = relu(acc @ W1 + b1); stage fp16; pack fp8
    uint2 pk[8];
#pragma unroll
    for (int ob = 0; ob < 8; ob++) {
        float o[8];
#pragma unroll
        for (int j = 0; j < 8; j++) {
            int c = ob * 8 + j;
            float t = bs[c];
            t += a0 * W1s[c];
            t += a1 * W1s[64 + c];
            t += a2 * W1s[128 + c];
            t += a3 * W1s[192 + c];
            t += a4 * W1s[256 + c];
            o[j] = (row < NN) ? fmaxf(t, 0.f) : 0.f;
        }
        uint4 sh;
        __half2 h;
        h = __floats2half2_rn(o[0], o[1]); sh.x = *(unsigned*)&h;
        h = __floats2half2_rn(o[2], o[3]); sh.y = *(unsigned*)&h;
        h = __floats2half2_rn(o[4], o[5]); sh.z = *(unsigned*)&h;
        h = __floats2half2_rn(o[6], o[7]); sh.w = *(unsigned*)&h;
        *(uint4*)&sp_h[tid * 72 + ob * 8] = sh;
        unsigned short s01 = f2_to_e4m3x2(o[1], o[0]);
        unsigned short s23 = f2_to_e4m3x2(o[3], o[2]);
        unsigned short s45 = f2_to_e4m3x2(o[5], o[4]);
        unsigned short s67 = f2_to_e4m3x2(o[7], o[6]);
        pk[ob].x = (unsigned)s01 | ((unsigned)s23 << 16);
        pk[ob].y = (unsigned)s45 | ((unsigned)s67 << 16);
    }
    if (row < NN) {
        uint4* dst = (uint4*)(g_x1f8 + (long)row * 8);
        dst[0] = make_uint4(pk[0].x, pk[0].y, pk[1].x, pk[1].y);
        dst[1] = make_uint4(pk[2].x, pk[2].y, pk[3].x, pk[3].y);
        dst[2] = make_uint4(pk[4].x, pk[4].y, pk[5].x, pk[5].y);
        dst[3] = make_uint4(pk[6].x, pk[6].y, pk[7].x, pk[7].y);
    }
    __syncthreads();
    if (tid < 64) {
        int rows_here = NN - base; if (rows_here > 128) rows_here = 128;
        float accum = 0.f;
        int gcur = sb[0];
        for (int nn = 0; nn < rows_here; nn++) {
            int g = sb[nn];
            if (g != gcur) {
                atomicAdd(&g_pool[gcur * 64 + tid], accum);
                gcur = g; accum = 0.f;
            }
            accum += __half2float(sp_h[nn * 72 + tid]);
        }
        if (rows_here > 0) atomicAdd(&g_pool[gcur * 64 + tid], accum);
    }
}

// ---------------- fused fp8 spmm + linear 64->64 + relu + pool ----------------
// 512 threads, 128 rows/block.
// Gather: 4 lanes/row, pipelined 2-pair loop (CSR prefetch one iteration ahead).
// GEMM: thread = (row pair, output octet), 2-row register blocking, f32x2 FMA.
// SRC=0: gather g_x1f8, write g_x2f8.  SRC=1: gather g_x2f8, no feature write.
template <int SRC>
__global__ void __launch_bounds__(512)
spmm_lin_kernel(const float* __restrict__ W, const float* __restrict__ b,
                const int* __restrict__ batch) {
    __shared__ float  Ws[64 * 64];      // 16 KB row-major [k][o]
    __shared__ __half ins_h[128 * 72];  // 18 KB fp16 staging
    __shared__ float  bs[64];
    __shared__ int    sb[128];
    int tid = threadIdx.x;
    for (int i = tid; i < 64 * 16; i += 512) ((float4*)Ws)[i] = ((const float4*)W)[i];
    if (tid < 64) bs[tid] = b[tid];
    int base = blockIdx.x * 128;
    if (tid >= 384) {
        int nd = base + (tid - 384);
        sb[tid - 384] = batch[nd < NN ? nd : (NN - 1)];
    }
    // ---- gather phase ----
    {
        int f = tid & 3;           // uint4 chunk (features f*16 .. f*16+15)
        int r = tid >> 2;          // 0..127
        int row = base + r;
        const uint4* __restrict__ xin = (const uint4*)(SRC == 0 ? g_x1f8 : g_x2f8);
        const int4* csr4 = (const int4*)g_csrcv;
        __half2 acc[8];
#pragma unroll
        for (int j = 0; j < 8; j++) acc[j] = __floats2half2_rn(0.f, 0.f);
        if (row < NN) {
            int start = g_rowptr[row];
            int npairs = (g_rowptr[row + 1] - start) >> 1;   // even
            int p2 = start >> 1;
            if (npairs > 0) {
                int4 cvA = __ldcs(&csr4[p2]);
                int4 cvB = __ldcs(&csr4[p2 + 1]);
                while (npairs > 2) {
                    int4 cvC = __ldcs(&csr4[p2 + 2]);
                    int4 cvD = __ldcs(&csr4[p2 + 3]);
                    uint4 a0 = xin[(long)cvA.x * 4 + f];
                    uint4 a1 = xin[(long)cvA.z * 4 + f];
                    uint4 a2 = xin[(long)cvB.x * 4 + f];
                    uint4 a3 = xin[(long)cvB.z * 4 + f];
                    F8_EDGEV(a0, cvA.y)
                    F8_EDGEV(a1, cvA.w)
                    F8_EDGEV(a2, cvB.y)
                    F8_EDGEV(a3, cvB.w)
                    cvA = cvC; cvB = cvD;
                    p2 += 2; npairs -= 2;
                }
                uint4 a0 = xin[(long)cvA.x * 4 + f];
                uint4 a1 = xin[(long)cvA.z * 4 + f];
                uint4 a2 = xin[(long)cvB.x * 4 + f];
                uint4 a3 = xin[(long)cvB.z * 4 + f];
                F8_EDGEV(a0, cvA.y)
                F8_EDGEV(a1, cvA.w)
                F8_EDGEV(a2, cvB.y)
                F8_EDGEV(a3, cvB.w)
            }
        }
        uint4 u0 = make_uint4(*(unsigned*)&acc[0], *(unsigned*)&acc[1],
                              *(unsigned*)&acc[2], *(unsigned*)&acc[3]);
        uint4 u1 = make_uint4(*(unsigned*)&acc[4], *(unsigned*)&acc[5],
                              *(unsigned*)&acc[6], *(unsigned*)&acc[7]);
        *(uint4*)&ins_h[r * 72 + f * 16 + 0] = u0;
        *(uint4*)&ins_h[r * 72 + f * 16 + 8] = u1;
    }
    __syncthreads();
    // ---- GEMM phase: thread = (row pair p, octet q); rows 2p, 2p+1 ----
    int p = tid >> 3;
    int q = tid & 7;             // outputs q*8 .. q*8+7
    int n0 = 2 * p, n1 = 2 * p + 1;
    unsigned long long a0[4], a1[4];
#pragma unroll
    for (int j = 0; j < 4; j++) {
        unsigned long long bj = pk2(bs[q * 8 + 2 * j], bs[q * 8 + 2 * j + 1]);
        a0[j] = bj; a1[j] = bj;
    }
    const ulonglong2* W64 = (const ulonglong2*)Ws;
#pragma unroll 4
    for (int k = 0; k < 64; k += 2) {
        unsigned xp0 = *(const unsigned*)&ins_h[n0 * 72 + k];
        unsigned xp1 = *(const unsigned*)&ins_h[n1 * 72 + k];
        float2 xf0 = __half22float2(*(__half2*)&xp0);
        float2 xf1 = __half22float2(*(__half2*)&xp1);
        ulonglong2 w0 = W64[k * 8 + q * 2 + 0];
        ulonglong2 w1 = W64[k * 8 + q * 2 + 1];
        ulonglong2 v0 = W64[(k + 1) * 8 + q * 2 + 0];
        ulonglong2 v1 = W64[(k + 1) * 8 + q * 2 + 1];
        unsigned long long x00 = pk2(xf0.x, xf0.x);
        unsigned long long x01 = pk2(xf0.y, xf0.y);
        unsigned long long x10 = pk2(xf1.x, xf1.x);
        unsigned long long x11 = pk2(xf1.y, xf1.y);
        a0[0] = fma2(x00, w0.x, a0[0]);
        a0[1] = fma2(x00, w0.y, a0[1]);
        a0[2] = fma2(x00, w1.x, a0[2]);
        a0[3] = fma2(x00, w1.y, a0[3]);
        a1[0] = fma2(x10, w0.x, a1[0]);
        a1[1] = fma2(x10, w0.y, a1[1]);
        a1[2] = fma2(x10, w1.x, a1[2]);
        a1[3] = fma2(x10, w1.y, a1[3]);
        a0[0] = fma2(x01, v0.x, a0[0]);
        a0[1] = fma2(x01, v0.y, a0[1]);
        a0[2] = fma2(x01, v1.x, a0[2]);
        a0[3] = fma2(x01, v1.y, a0[3]);
        a1[0] = fma2(x11, v0.x, a1[0]);
        a1[1] = fma2(x11, v0.y, a1[1]);
        a1[2] = fma2(x11, v1.x, a1[2]);
        a1[3] = fma2(x11, v1.y, a1[3]);
    }
    float o0[8], o1[8];
#pragma unroll
    for (int j = 0; j < 4; j++) {
        upk2(a0[j], o0[2 * j], o0[2 * j + 1]);
        upk2(a1[j], o1[2 * j], o1[2 * j + 1]);
    }
#pragma unroll
    for (int j = 0; j < 8; j++) { o0[j] = fmaxf(o0[j], 0.f); o1[j] = fmaxf(o1[j], 0.f); }
    int node0 = base + n0, node1 = base + n1;
    if (SRC == 0) {
        if (node0 < NN) {
            uint2 w;
            w.x = (unsigned)f2_to_e4m3x2(o0[1], o0[0]) | ((unsigned)f2_to_e4m3x2(o0[3], o0[2]) << 16);
            w.y = (unsigned)f2_to_e4m3x2(o0[5], o0[4]) | ((unsigned)f2_to_e4m3x2(o0[7], o0[6]) << 16);
            g_x2f8[(long)node0 * 8 + q] = w;
        }
        if (node1 < NN) {
            uint2 w;
            w.x = (unsigned)f2_to_e4m3x2(o1[1], o1[0]) | ((unsigned)f2_to_e4m3x2(o1[3], o1[2]) << 16);
            w.y = (unsigned)f2_to_e4m3x2(o1[5], o1[4]) | ((unsigned)f2_to_e4m3x2(o1[7], o1[6]) << 16);
            g_x2f8[(long)node1 * 8 + q] = w;
        }
    }
    // ---- pool staging (reuse ins_h) ----
    __syncthreads();
    {
        if (node0 >= NN) { o0[0]=o0[1]=o0[2]=o0[3]=o0[4]=o0[5]=o0[6]=o0[7]=0.f; }
        if (node1 >= NN) { o1[0]=o1[1]=o1[2]=o1[3]=o1[4]=o1[5]=o1[6]=o1[7]=0.f; }
        uint4 s0, s1;
        __half2 h;
        h = __floats2half2_rn(o0[0], o0[1]); s0.x = *(unsigned*)&h;
        h = __floats2half2_rn(o0[2], o0[3]); s0.y = *(unsigned*)&h;
        h = __floats2half2_rn(o0[4], o0[5]); s0.z = *(unsigned*)&h;
        h = __floats2half2_rn(o0[6], o0[7]); s0.w = *(unsigned*)&h;
        h = __floats2half2_rn(o1[0], o1[1]); s1.x = *(unsigned*)&h;
        h = __floats2half2_rn(o1[2], o1[3]); s1.y = *(unsigned*)&h;
        h = __floats2half2_rn(o1[4], o1[5]); s1.z = *(unsigned*)&h;
        h = __floats2half2_rn(o1[6], o1[7]); s1.w = *(unsigned*)&h;
        *(uint4*)&ins_h[n0 * 72 + q * 8] = s0;
        *(uint4*)&ins_h[n1 * 72 + q * 8] = s1;
    }
    __syncthreads();
    if (tid < 64) {
        int rows_here = NN - base; if (rows_here > 128) rows_here = 128;
        float accum = 0.f;
        int gcur = sb[0];
        for (int nn = 0; nn < rows_here; nn++) {
            int g = sb[nn];
            if (g != gcur) {
                atomicAdd(&g_pool[gcur * 64 + tid], accum);
                gcur = g; accum = 0.f;
            }
            accum += __half2float(ins_h[nn * 72 + tid]);
        }
        if (rows_here > 0) atomicAdd(&g_pool[gcur * 64 + tid], accum);
    }
}

// ---------------- final linear 64->10 + softmax ----------------
__global__ void final_kernel(const int* __restrict__ batch,
                             const float* __restrict__ Wl, const float* __restrict__ bl,
                             float* __restrict__ out) {
    __shared__ float Ws[64 * 10];
    __shared__ float bs[10];
    int tid = threadIdx.x;
    for (int i = tid; i < 640; i += 256) Ws[i] = Wl[i];
    if (tid < 10) bs[tid] = bl[tid];
    __syncthreads();
    int g = tid;
    int lo = 0, hi = NN;
    while (lo < hi) { int mid = (lo + hi) >> 1; if (batch[mid] < g) lo = mid + 1; else hi = mid; }
    int lb = lo;
    lo = 0; hi = NN;
    while (lo < hi) { int mid = (lo + hi) >> 1; if (batch[mid] < g + 1) lo = mid + 1; else hi = mid; }
    float cnt = (float)(lo - lb);
    float inv = 1.0f / (3.0f * fmaxf(cnt, 1.0f));
    float logits[10];
#pragma unroll
    for (int o = 0; o < 10; o++) logits[o] = bs[o];
    for (int f = 0; f < 64; f++) {
        float m = g_pool[g * 64 + f] * inv;
#pragma unroll
        for (int o = 0; o < 10; o++) logits[o] += m * Ws[f * 10 + o];
    }
    float mx = logits[0];
#pragma unroll
    for (int o = 1; o < 10; o++) mx = fmaxf(mx, logits[o]);
    float sum = 0.f;
#pragma unroll
    for (int o = 0; o < 10; o++) { logits[o] = expf(logits[o] - mx); sum += logits[o]; }
    float is = 1.0f / sum;
#pragma unroll
    for (int o = 0; o < 10; o++) out[g * 10 + o] = logits[o] * is;
}

// ---------------- launch ----------------
extern "C" void kernel_launch(void* const* d_in, const int* in_sizes, int n_in,
                              void* d_out, int out_size) {
    const float* x    = (const float*)d_in[0];
    const int*   rows = (const int*)d_in[1];
    const int*   cols = (const int*)d_in[2];
    const float* vals = (const float*)d_in[3];
    const int*   batch= (const int*)d_in[4];
    const float* W1 = (const float*)d_in[5];
    const float* b1 = (const float*)d_in[6];
    const float* W2 = (const float*)d_in[7];
    const float* b2 = (const float*)d_in[8];
    const float* W3 = (const float*)d_in[9];
    const float* b3 = (const float*)d_in[10];
    const float* Wl = (const float*)d_in[11];
    const float* bl = (const float*)d_in[12];
    float* out = (float*)d_out;

    zero_pack_kernel<<<(NN + 255) / 256, 256>>>(x);
    hist_kernel<<<(NE / 4 + 255) / 256, 256>>>((const int4*)rows);
    scanA_kernel<<<NB_SCAN, 512>>>();
    scanC_kernel<<<NB_SCAN, 512>>>();
    scatter_kernel<<<(NE / 4 + 255) / 256, 256>>>((const int4*)rows, (const int4*)cols,
                                                  (const float4*)vals);

    spmm_l1_kernel<<<(NN + 127) / 128, 128>>>(W1, b1, batch);      // x1 -> fp8 + pool
    spmm_lin_kernel<0><<<(NN + 127) / 128, 512>>>(W2, b2, batch);  // x2 -> fp8 + pool
    spmm_lin_kernel<1><<<(NN + 127) / 128, 512>>>(W3, b3, batch);  // x3 -> pool

    final_kernel<<<1, 256>>>(batch, Wl, bl, out);
}

// round 15
// speedup vs baseline: 1.0286x; 1.0286x over previous
#include <cuda_runtime.h>
#include <cuda_fp16.h>

#define NN 100000
#define NE 3200000
#define NG 256
#define NB_SCAN 196   // ceil(NN/512)

// ---------------- static scratch ----------------
__device__ int    g_deg[NN];
__device__ int    g_rowptr[NN + 1];      // even-aligned row starts
__device__ int    g_bsum[NB_SCAN];
__device__ int4   g_rank4[NE / 4];       // per-edge rank within its row
__device__ int2   g_csrcv[NE + NN];      // (col, val as half2(v,v)) CSR, rows padded even
__device__ uint4  g_xpack[NN];           // x packed: 5 x fp16 + pad (16B/node)
__device__ uint2  g_x1f8[NN * 8];        // x1 fp8 e4m3 [NN,64]
__device__ uint2  g_x2f8[NN * 8];        // x2 fp8 e4m3 [NN,64]
__device__ float  g_pool[NG * 64];

// ---------------- f32x2 helpers ----------------
static __forceinline__ __device__ unsigned long long pk2(float lo, float hi) {
    unsigned long long r;
    asm("mov.b64 %0,{%1,%2};" : "=l"(r) : "f"(lo), "f"(hi));
    return r;
}
static __forceinline__ __device__ unsigned long long fma2(unsigned long long a,
                                                          unsigned long long b,
                                                          unsigned long long c) {
    unsigned long long d;
    asm("fma.rn.f32x2 %0,%1,%2,%3;" : "=l"(d) : "l"(a), "l"(b), "l"(c));
    return d;
}
static __forceinline__ __device__ void upk2(unsigned long long v, float& lo, float& hi) {
    asm("mov.b64 {%0,%1},%2;" : "=f"(lo), "=f"(hi) : "l"(v));
}

// ---------------- fp8 helpers ----------------
static __forceinline__ __device__ __half2 e4m3x2_to_h2(unsigned short u) {
    unsigned int r;
    asm("cvt.rn.f16x2.e4m3x2 %0, %1;" : "=r"(r) : "h"(u));
    return *(__half2*)&r;
}
static __forceinline__ __device__ unsigned short f2_to_e4m3x2(float hi, float lo) {
    unsigned short r;
    asm("cvt.rn.satfinite.e4m3x2.f32 %0, %1, %2;" : "=h"(r) : "f"(hi), "f"(lo));
    return r;
}

// edge-accumulate macros (VB = half2(v,v) bits)
#define L1_EDGEV(XA, VB) { \
    unsigned vb_ = (unsigned)(VB); \
    float v = __half2float(*(__half*)&vb_); \
    float2 p01 = __half22float2(*(__half2*)&XA.x); \
    float2 p23 = __half22float2(*(__half2*)&XA.y); \
    float2 p4x = __half22float2(*(__half2*)&XA.z); \
    a0 += v * p01.x; a1 += v * p01.y; a2 += v * p23.x; \
    a3 += v * p23.y; a4 += v * p4x.x; }

#define F8_EDGEV(AA, VB) { \
    unsigned vb_ = (unsigned)(VB); \
    __half2 v2 = *(__half2*)&vb_; \
    acc[0] = __hfma2(v2, e4m3x2_to_h2((unsigned short)(AA.x & 0xffff)), acc[0]); \
    acc[1] = __hfma2(v2, e4m3x2_to_h2((unsigned short)(AA.x >> 16)), acc[1]); \
    acc[2] = __hfma2(v2, e4m3x2_to_h2((unsigned short)(AA.y & 0xffff)), acc[2]); \
    acc[3] = __hfma2(v2, e4m3x2_to_h2((unsigned short)(AA.y >> 16)), acc[3]); \
    acc[4] = __hfma2(v2, e4m3x2_to_h2((unsigned short)(AA.z & 0xffff)), acc[4]); \
    acc[5] = __hfma2(v2, e4m3x2_to_h2((unsigned short)(AA.z >> 16)), acc[5]); \
    acc[6] = __hfma2(v2, e4m3x2_to_h2((unsigned short)(AA.w & 0xffff)), acc[6]); \
    acc[7] = __hfma2(v2, e4m3x2_to_h2((unsigned short)(AA.w >> 16)), acc[7]); }

// ---------------- zero + pack x ----------------
__global__ void zero_pack_kernel(const float* __restrict__ x) {
    int i = blockIdx.x * blockDim.x + threadIdx.x;
    if (i < NN) {
        g_deg[i] = 0;
        const float* xr = x + (long)i * 5;
        uint4 u;
        *(__half2*)&u.x = __floats2half2_rn(xr[0], xr[1]);
        *(__half2*)&u.y = __floats2half2_rn(xr[2], xr[3]);
        *(__half2*)&u.z = __floats2half2_rn(xr[4], 0.f);
        u.w = 0;
        g_xpack[i] = u;
    }
    if (i < NG * 64) g_pool[i] = 0.f;
}

// ---------------- CSR build ----------------
__global__ void hist_kernel(const int4* __restrict__ rows4) {
    int i = blockIdx.x * blockDim.x + threadIdx.x;
    if (i < NE / 4) {
        int4 r = rows4[i];
        int4 k;
        k.x = atomicAdd(&g_deg[r.x], 1);
        k.y = atomicAdd(&g_deg[r.y], 1);
        k.z = atomicAdd(&g_deg[r.z], 1);
        k.w = atomicAdd(&g_deg[r.w], 1);
        g_rank4[i] = k;
    }
}

__global__ void scanA_kernel() {
    __shared__ int s[512];
    int t = threadIdx.x;
    int i = blockIdx.x * 512 + t;
    s[t] = (i < NN) ? ((g_deg[i] + 1) & ~1) : 0;   // padded degrees (even)
    __syncthreads();
    for (int off = 256; off > 0; off >>= 1) {
        if (t < off) s[t] += s[t + off];
        __syncthreads();
    }
    if (t == 0) g_bsum[blockIdx.x] = s[0];
}

// per-block base + in-block scan over PADDED degrees -> rowptr; zero pad slots
__global__ void scanC_kernel() {
    __shared__ int rs[512];
    __shared__ int s[512];
    __shared__ int sbase;
    int t = threadIdx.x;
    int bid = blockIdx.x;
    int part = (t < bid) ? g_bsum[t] : 0;
    rs[t] = part;
    __syncthreads();
    for (int off = 256; off > 0; off >>= 1) {
        if (t < off) rs[t] += rs[t + off];
        __syncthreads();
    }
    if (t == 0) sbase = rs[0];
    int i = bid * 512 + t;
    int d = (i < NN) ? g_deg[i] : 0;
    int dp = (d + 1) & ~1;
    s[t] = dp;
    __syncthreads();
    for (int off = 1; off < 512; off <<= 1) {
        int v = 0;
        if (t >= off) v = s[t - off];
        __syncthreads();
        if (t >= off) s[t] += v;
        __syncthreads();
    }
    int incl = s[t];
    if (i < NN) {
        int p = sbase + incl - dp;
        g_rowptr[i] = p;
        if (d & 1) g_csrcv[p + d] = make_int2(0, 0);   // zero the pad slot
        if (i == NN - 1) g_rowptr[NN] = sbase + incl;
    }
}

// rank-based scatter; val stored pre-packed as half2(v,v)
__global__ void scatter_kernel(const int4* __restrict__ rows4,
                               const int4* __restrict__ cols4,
                               const float4* __restrict__ vals4) {
    int i = blockIdx.x * blockDim.x + threadIdx.x;
    if (i < NE / 4) {
        int4 r = rows4[i];
        int4 c = cols4[i];
        float4 v = vals4[i];
        int4 k = g_rank4[i];
        int p0 = __ldg(&g_rowptr[r.x]) + k.x;
        int p1 = __ldg(&g_rowptr[r.y]) + k.y;
        int p2 = __ldg(&g_rowptr[r.z]) + k.z;
        int p3 = __ldg(&g_rowptr[r.w]) + k.w;
        __half2 h0 = __float2half2_rn(v.x);
        __half2 h1 = __float2half2_rn(v.y);
        __half2 h2 = __float2half2_rn(v.z);
        __half2 h3 = __float2half2_rn(v.w);
        g_csrcv[p0] = make_int2(c.x, *(int*)&h0);
        g_csrcv[p1] = make_int2(c.y, *(int*)&h1);
        g_csrcv[p2] = make_int2(c.z, *(int*)&h2);
        g_csrcv[p3] = make_int2(c.w, *(int*)&h3);
    }
}

// ---------------- layer 1: row-per-thread spmm(x), int4 cv loads, MLP 8 ----------
__global__ void __launch_bounds__(128)
spmm_l1_kernel(const float* __restrict__ W1, const float* __restrict__ b1,
               const int* __restrict__ batch) {
    __shared__ float  W1s[320];
    __shared__ float  bs[64];
    __shared__ __half sp_h[128 * 72];   // fp16 staging, padded stride 72
    __shared__ int    sb[128];
    int tid = threadIdx.x;
    for (int i = tid; i < 320; i += 128) W1s[i] = W1[i];
    if (tid < 64) bs[tid] = b1[tid];
    int base = blockIdx.x * 128;
    {
        int nd = base + tid;
        sb[tid] = batch[nd < NN ? nd : (NN - 1)];
    }
    __syncthreads();
    int row = base + tid;
    float a0 = 0, a1 = 0, a2 = 0, a3 = 0, a4 = 0;
    if (row < NN) {
        const int4* csr4 = (const int4*)g_csrcv;
        int start = g_rowptr[row];
        int deg = g_deg[row];
        int p2 = start >> 1;
        int np = (deg + 1) >> 1;          // pairs (padded)
        for (; np >= 4; np -= 4, p2 += 4) {
            int4 cvA = __ldcs(&csr4[p2]);
            int4 cvB = __ldcs(&csr4[p2 + 1]);
            int4 cvC = __ldcs(&csr4[p2 + 2]);
            int4 cvD = __ldcs(&csr4[p2 + 3]);
            uint4 x0 = g_xpack[cvA.x];
            uint4 x1 = g_xpack[cvA.z];
            uint4 x2 = g_xpack[cvB.x];
            uint4 x3 = g_xpack[cvB.z];
            uint4 x4 = g_xpack[cvC.x];
            uint4 x5 = g_xpack[cvC.z];
            uint4 x6 = g_xpack[cvD.x];
            uint4 x7 = g_xpack[cvD.z];
            L1_EDGEV(x0, cvA.y)
            L1_EDGEV(x1, cvA.w)
            L1_EDGEV(x2, cvB.y)
            L1_EDGEV(x3, cvB.w)
            L1_EDGEV(x4, cvC.y)
            L1_EDGEV(x5, cvC.w)
            L1_EDGEV(x6, cvD.y)
            L1_EDGEV(x7, cvD.w)
        }
        for (; np > 0; np--, p2++) {
            int4 cvA = __ldcs(&csr4[p2]);
            uint4 x0 = g_xpack[cvA.x];
            uint4 x1 = g_xpack[cvA.z];
            L1_EDGEV(x0, cvA.y)
            L1_EDGEV(x1, cvA.w)
        }
    }
    // epilogue: out = relu(acc @ W1 + b1); stage fp16; pack fp8
    uint2 pk[8];
#pragma unroll
    for (int ob = 0; ob < 8; ob++) {
        float o[8];
#pragma unroll
        for (int j = 0; j < 8; j++) {
            int c = ob * 8 + j;
            float t = bs[c];
            t += a0 * W1s[c];
            t += a1 * W1s[64 + c];
            t += a2 * W1s[128 + c];
            t += a3 * W1s[192 + c];
            t += a4 * W1s[256 + c];
            o[j] = (row < NN) ? fmaxf(t, 0.f) : 0.f;
        }
        uint4 sh;
        __half2 h;
        h = __floats2half2_rn(o[0], o[1]); sh.x = *(unsigned*)&h;
        h = __floats2half2_rn(o[2], o[3]); sh.y = *(unsigned*)&h;
        h = __floats2half2_rn(o[4], o[5]); sh.z = *(unsigned*)&h;
        h = __floats2half2_rn(o[6], o[7]); sh.w = *(unsigned*)&h;
        *(uint4*)&sp_h[tid * 72 + ob * 8] = sh;
        unsigned short s01 = f2_to_e4m3x2(o[1], o[0]);
        unsigned short s23 = f2_to_e4m3x2(o[3], o[2]);
        unsigned short s45 = f2_to_e4m3x2(o[5], o[4]);
        unsigned short s67 = f2_to_e4m3x2(o[7], o[6]);
        pk[ob].x = (unsigned)s01 | ((unsigned)s23 << 16);
        pk[ob].y = (unsigned)s45 | ((unsigned)s67 << 16);
    }
    if (row < NN) {
        uint4* dst = (uint4*)(g_x1f8 + (long)row * 8);
        dst[0] = make_uint4(pk[0].x, pk[0].y, pk[1].x, pk[1].y);
        dst[1] = make_uint4(pk[2].x, pk[2].y, pk[3].x, pk[3].y);
        dst[2] = make_uint4(pk[4].x, pk[4].y, pk[5].x, pk[5].y);
        dst[3] = make_uint4(pk[6].x, pk[6].y, pk[7].x, pk[7].y);
    }
    __syncthreads();
    // parallel pool: 128 threads = 2 row-halves x 64 features
    {
        int half = tid >> 6;            // 0..1
        int fidx = tid & 63;
        int rbeg = half * 64;
        int rend = rbeg + 64;
        int rows_here = NN - base; if (rows_here > 128) rows_here = 128;
        if (rend > rows_here) rend = rows_here;
        if (rbeg < rend) {
            float accum = 0.f;
            int gcur = sb[rbeg];
            for (int nn = rbeg; nn < rend; nn++) {
                int g = sb[nn];
                if (g != gcur) {
                    atomicAdd(&g_pool[gcur * 64 + fidx], accum);
                    gcur = g; accum = 0.f;
                }
                accum += __half2float(sp_h[nn * 72 + fidx]);
            }
            atomicAdd(&g_pool[gcur * 64 + fidx], accum);
        }
    }
}

// ---------------- fused fp8 spmm + linear 64->64 + relu + pool ----------------
// 512 threads, 128 rows/block.
// Gather: 4 lanes/row, int4 cv (2 edges/load, streaming) + uint4 features, fp16 accum.
// GEMM: thread = (row pair, output octet), 2-row register blocking, f32x2 FMA.
// SRC=0: gather g_x1f8, write g_x2f8.  SRC=1: gather g_x2f8, no feature write.
template <int SRC>
__global__ void __launch_bounds__(512)
spmm_lin_kernel(const float* __restrict__ W, const float* __restrict__ b,
                const int* __restrict__ batch) {
    __shared__ float  Ws[64 * 64];      // 16 KB row-major [k][o]
    __shared__ __half ins_h[128 * 72];  // 18 KB fp16 staging
    __shared__ float  bs[64];
    __shared__ int    sb[128];
    int tid = threadIdx.x;
    for (int i = tid; i < 64 * 16; i += 512) ((float4*)Ws)[i] = ((const float4*)W)[i];
    if (tid < 64) bs[tid] = b[tid];
    int base = blockIdx.x * 128;
    if (tid >= 384) {
        int nd = base + (tid - 384);
        sb[tid - 384] = batch[nd < NN ? nd : (NN - 1)];
    }
    // ---- gather phase ----
    {
        int f = tid & 3;           // uint4 chunk (features f*16 .. f*16+15)
        int r = tid >> 2;          // 0..127
        int row = base + r;
        const uint4* __restrict__ xin = (const uint4*)(SRC == 0 ? g_x1f8 : g_x2f8);
        const int4* csr4 = (const int4*)g_csrcv;
        __half2 acc[8];
#pragma unroll
        for (int j = 0; j < 8; j++) acc[j] = __floats2half2_rn(0.f, 0.f);
        if (row < NN) {
            int start = g_rowptr[row];
            int deg = g_deg[row];
            int p2 = start >> 1;
            int np = (deg + 1) >> 1;      // pairs (padded)
            for (; np >= 2; np -= 2, p2 += 2) {
                int4 cvA = __ldcs(&csr4[p2]);
                int4 cvB = __ldcs(&csr4[p2 + 1]);
                uint4 a0 = xin[(long)cvA.x * 4 + f];
                uint4 a1 = xin[(long)cvA.z * 4 + f];
                uint4 a2 = xin[(long)cvB.x * 4 + f];
                uint4 a3 = xin[(long)cvB.z * 4 + f];
                F8_EDGEV(a0, cvA.y)
                F8_EDGEV(a1, cvA.w)
                F8_EDGEV(a2, cvB.y)
                F8_EDGEV(a3, cvB.w)
            }
            if (np > 0) {
                int4 cvA = __ldcs(&csr4[p2]);
                uint4 a0 = xin[(long)cvA.x * 4 + f];
                uint4 a1 = xin[(long)cvA.z * 4 + f];
                F8_EDGEV(a0, cvA.y)
                F8_EDGEV(a1, cvA.w)
            }
        }
        uint4 u0 = make_uint4(*(unsigned*)&acc[0], *(unsigned*)&acc[1],
                              *(unsigned*)&acc[2], *(unsigned*)&acc[3]);
        uint4 u1 = make_uint4(*(unsigned*)&acc[4], *(unsigned*)&acc[5],
                              *(unsigned*)&acc[6], *(unsigned*)&acc[7]);
        *(uint4*)&ins_h[r * 72 + f * 16 + 0] = u0;
        *(uint4*)&ins_h[r * 72 + f * 16 + 8] = u1;
    }
    __syncthreads();
    // ---- GEMM phase: thread = (row pair p, octet q); rows 2p, 2p+1 ----
    int p = tid >> 3;
    int q = tid & 7;             // outputs q*8 .. q*8+7
    int n0 = 2 * p, n1 = 2 * p + 1;
    unsigned long long a0[4], a1[4];
#pragma unroll
    for (int j = 0; j < 4; j++) {
        unsigned long long bj = pk2(bs[q * 8 + 2 * j], bs[q * 8 + 2 * j + 1]);
        a0[j] = bj; a1[j] = bj;
    }
    const ulonglong2* W64 = (const ulonglong2*)Ws;
#pragma unroll 4
    for (int k = 0; k < 64; k += 2) {
        unsigned xp0 = *(const unsigned*)&ins_h[n0 * 72 + k];
        unsigned xp1 = *(const unsigned*)&ins_h[n1 * 72 + k];
        float2 xf0 = __half22float2(*(__half2*)&xp0);
        float2 xf1 = __half22float2(*(__half2*)&xp1);
        ulonglong2 w0 = W64[k * 8 + q * 2 + 0];
        ulonglong2 w1 = W64[k * 8 + q * 2 + 1];
        ulonglong2 v0 = W64[(k + 1) * 8 + q * 2 + 0];
        ulonglong2 v1 = W64[(k + 1) * 8 + q * 2 + 1];
        unsigned long long x00 = pk2(xf0.x, xf0.x);
        unsigned long long x01 = pk2(xf0.y, xf0.y);
        unsigned long long x10 = pk2(xf1.x, xf1.x);
        unsigned long long x11 = pk2(xf1.y, xf1.y);
        a0[0] = fma2(x00, w0.x, a0[0]);
        a0[1] = fma2(x00, w0.y, a0[1]);
        a0[2] = fma2(x00, w1.x, a0[2]);
        a0[3] = fma2(x00, w1.y, a0[3]);
        a1[0] = fma2(x10, w0.x, a1[0]);
        a1[1] = fma2(x10, w0.y, a1[1]);
        a1[2] = fma2(x10, w1.x, a1[2]);
        a1[3] = fma2(x10, w1.y, a1[3]);
        a0[0] = fma2(x01, v0.x, a0[0]);
        a0[1] = fma2(x01, v0.y, a0[1]);
        a0[2] = fma2(x01, v1.x, a0[2]);
        a0[3] = fma2(x01, v1.y, a0[3]);
        a1[0] = fma2(x11, v0.x, a1[0]);
        a1[1] = fma2(x11, v0.y, a1[1]);
        a1[2] = fma2(x11, v1.x, a1[2]);
        a1[3] = fma2(x11, v1.y, a1[3]);
    }
    float o0[8], o1[8];
#pragma unroll
    for (int j = 0; j < 4; j++) {
        upk2(a0[j], o0[2 * j], o0[2 * j + 1]);
        upk2(a1[j], o1[2 * j], o1[2 * j + 1]);
    }
#pragma unroll
    for (int j = 0; j < 8; j++) { o0[j] = fmaxf(o0[j], 0.f); o1[j] = fmaxf(o1[j], 0.f); }
    int node0 = base + n0, node1 = base + n1;
    if (SRC == 0) {
        if (node0 < NN) {
            uint2 w;
            w.x = (unsigned)f2_to_e4m3x2(o0[1], o0[0]) | ((unsigned)f2_to_e4m3x2(o0[3], o0[2]) << 16);
            w.y = (unsigned)f2_to_e4m3x2(o0[5], o0[4]) | ((unsigned)f2_to_e4m3x2(o0[7], o0[6]) << 16);
            g_x2f8[(long)node0 * 8 + q] = w;
        }
        if (node1 < NN) {
            uint2 w;
            w.x = (unsigned)f2_to_e4m3x2(o1[1], o1[0]) | ((unsigned)f2_to_e4m3x2(o1[3], o1[2]) << 16);
            w.y = (unsigned)f2_to_e4m3x2(o1[5], o1[4]) | ((unsigned)f2_to_e4m3x2(o1[7], o1[6]) << 16);
            g_x2f8[(long)node1 * 8 + q] = w;
        }
    }
    // ---- pool staging (reuse ins_h) ----
    __syncthreads();
    {
        if (node0 >= NN) { o0[0]=o0[1]=o0[2]=o0[3]=o0[4]=o0[5]=o0[6]=o0[7]=0.f; }
        if (node1 >= NN) { o1[0]=o1[1]=o1[2]=o1[3]=o1[4]=o1[5]=o1[6]=o1[7]=0.f; }
        uint4 s0, s1;
        __half2 h;
        h = __floats2half2_rn(o0[0], o0[1]); s0.x = *(unsigned*)&h;
        h = __floats2half2_rn(o0[2], o0[3]); s0.y = *(unsigned*)&h;
        h = __floats2half2_rn(o0[4], o0[5]); s0.z = *(unsigned*)&h;
        h = __floats2half2_rn(o0[6], o0[7]); s0.w = *(unsigned*)&h;
        h = __floats2half2_rn(o1[0], o1[1]); s1.x = *(unsigned*)&h;
        h = __floats2half2_rn(o1[2], o1[3]); s1.y = *(unsigned*)&h;
        h = __floats2half2_rn(o1[4], o1[5]); s1.z = *(unsigned*)&h;
        h = __floats2half2_rn(o1[6], o1[7]); s1.w = *(unsigned*)&h;
        *(uint4*)&ins_h[n0 * 72 + q * 8] = s0;
        *(uint4*)&ins_h[n1 * 72 + q * 8] = s1;
    }
    __syncthreads();
    // parallel pool: 256 threads = 4 row-quarters x 64 features
    if (tid < 256) {
        int quarter = tid >> 6;          // 0..3
        int fidx = tid & 63;
        int rbeg = quarter * 32;
        int rend = rbeg + 32;
        int rows_here = NN - base; if (rows_here > 128) rows_here = 128;
        if (rend > rows_here) rend = rows_here;
        if (rbeg < rend) {
            float accum = 0.f;
            int gcur = sb[rbeg];
            for (int nn = rbeg; nn < rend; nn++) {
                int g = sb[nn];
                if (g != gcur) {
                    atomicAdd(&g_pool[gcur * 64 + fidx], accum);
                    gcur = g; accum = 0.f;
                }
                accum += __half2float(ins_h[nn * 72 + fidx]);
            }
            atomicAdd(&g_pool[gcur * 64 + fidx], accum);
        }
    }
}

// ---------------- final linear 64->10 + softmax ----------------
__global__ void final_kernel(const int* __restrict__ batch,
                             const float* __restrict__ Wl, const float* __restrict__ bl,
                             float* __restrict__ out) {
    __shared__ float Ws[64 * 10];
    __shared__ float bs[10];
    int tid = threadIdx.x;
    for (int i = tid; i < 640; i += 256) Ws[i] = Wl[i];
    if (tid < 10) bs[tid] = bl[tid];
    __syncthreads();
    int g = tid;
    int lo = 0, hi = NN;
    while (lo < hi) { int mid = (lo + hi) >> 1; if (batch[mid] < g) lo = mid + 1; else hi = mid; }
    int lb = lo;
    lo = 0; hi = NN;
    while (lo < hi) { int mid = (lo + hi) >> 1; if (batch[mid] < g + 1) lo = mid + 1; else hi = mid; }
    float cnt = (float)(lo - lb);
    float inv = 1.0f / (3.0f * fmaxf(cnt, 1.0f));
    float logits[10];
#pragma unroll
    for (int o = 0; o < 10; o++) logits[o] = bs[o];
    for (int f = 0; f < 64; f++) {
        float m = g_pool[g * 64 + f] * inv;
#pragma unroll
        for (int o = 0; o < 10; o++) logits[o] += m * Ws[f * 10 + o];
    }
    float mx = logits[0];
#pragma unroll
    for (int o = 1; o < 10; o++) mx = fmaxf(mx, logits[o]);
    float sum = 0.f;
#pragma unroll
    for (int o = 0; o < 10; o++) { logits[o] = expf(logits[o] - mx); sum += logits[o]; }
    float is = 1.0f / sum;
#pragma unroll
    for (int o = 0; o < 10; o++) out[g * 10 + o] = logits[o] * is;
}

// ---------------- launch ----------------
extern "C" void kernel_launch(void* const* d_in, const int* in_sizes, int n_in,
                              void* d_out, int out_size) {
    const float* x    = (const float*)d_in[0];
    const int*   rows = (const int*)d_in[1];
    const int*   cols = (const int*)d_in[2];
    const float* vals = (const float*)d_in[3];
    const int*   batch= (const int*)d_in[4];
    const float* W1 = (const float*)d_in[5];
    const float* b1 = (const float*)d_in[6];
    const float* W2 = (const float*)d_in[7];
    const float* b2 = (const float*)d_in[8];
    const float* W3 = (const float*)d_in[9];
    const float* b3 = (const float*)d_in[10];
    const float* Wl = (const float*)d_in[11];
    const float* bl = (const float*)d_in[12];
    float* out = (float*)d_out;

    zero_pack_kernel<<<(NN + 255) / 256, 256>>>(x);
    hist_kernel<<<(NE / 4 + 255) / 256, 256>>>((const int4*)rows);
    scanA_kernel<<<NB_SCAN, 512>>>();
    scanC_kernel<<<NB_SCAN, 512>>>();
    scatter_kernel<<<(NE / 4 + 255) / 256, 256>>>((const int4*)rows, (const int4*)cols,
                                                  (const float4*)vals);

    spmm_l1_kernel<<<(NN + 127) / 128, 128>>>(W1, b1, batch);      // x1 -> fp8 + pool
    spmm_lin_kernel<0><<<(NN + 127) / 128, 512>>>(W2, b2, batch);  // x2 -> fp8 + pool
    spmm_lin_kernel<1><<<(NN + 127) / 128, 512>>>(W3, b3, batch);  // x3 -> pool

    final_kernel<<<1, 256>>>(batch, Wl, bl, out);
}

// round 16
// speedup vs baseline: 1.0288x; 1.0002x over previous
#include <cuda_runtime.h>
#include <cuda_fp16.h>

#define NN 100000
#define NE 3200000
#define NG 256
#define NB_SCAN 196   // ceil(NN/512)

// ---------------- static scratch ----------------
__device__ int    g_deg[NN];
__device__ int    g_rowptr[NN + 1];      // even-aligned row starts
__device__ int    g_bsum[NB_SCAN];
__device__ int4   g_rank4[NE / 4];       // per-edge rank within its row
__device__ int2   g_csrcv[NE + NN];      // (col, val as half2(v,v)) CSR, rows padded even
__device__ uint4  g_xpack[NN];           // x packed: 5 x fp16 + pad (16B/node)
__device__ uint2  g_x1f8[NN * 8];        // x1 fp8 e4m3 [NN,64]
__device__ uint2  g_x2f8[NN * 8];        // x2 fp8 e4m3 [NN,64]
__device__ float  g_pool[NG * 64];

// ---------------- f32x2 helpers ----------------
static __forceinline__ __device__ unsigned long long pk2(float lo, float hi) {
    unsigned long long r;
    asm("mov.b64 %0,{%1,%2};" : "=l"(r) : "f"(lo), "f"(hi));
    return r;
}
static __forceinline__ __device__ unsigned long long fma2(unsigned long long a,
                                                          unsigned long long b,
                                                          unsigned long long c) {
    unsigned long long d;
    asm("fma.rn.f32x2 %0,%1,%2,%3;" : "=l"(d) : "l"(a), "l"(b), "l"(c));
    return d;
}
static __forceinline__ __device__ void upk2(unsigned long long v, float& lo, float& hi) {
    asm("mov.b64 {%0,%1},%2;" : "=f"(lo), "=f"(hi) : "l"(v));
}

// ---------------- fp8 helpers ----------------
static __forceinline__ __device__ __half2 e4m3x2_to_h2(unsigned short u) {
    unsigned int r;
    asm("cvt.rn.f16x2.e4m3x2 %0, %1;" : "=r"(r) : "h"(u));
    return *(__half2*)&r;
}
static __forceinline__ __device__ unsigned short f2_to_e4m3x2(float hi, float lo) {
    unsigned short r;
    asm("cvt.rn.satfinite.e4m3x2.f32 %0, %1, %2;" : "=h"(r) : "f"(hi), "f"(lo));
    return r;
}

// edge-accumulate macros (VB = half2(v,v) bits)
#define L1_EDGEV(XA, VB) { \
    unsigned vb_ = (unsigned)(VB); \
    float v = __half2float(*(__half*)&vb_); \
    float2 p01 = __half22float2(*(__half2*)&XA.x); \
    float2 p23 = __half22float2(*(__half2*)&XA.y); \
    float2 p4x = __half22float2(*(__half2*)&XA.z); \
    a0 += v * p01.x; a1 += v * p01.y; a2 += v * p23.x; \
    a3 += v * p23.y; a4 += v * p4x.x; }

#define F8_EDGEV(AA, VB) { \
    unsigned vb_ = (unsigned)(VB); \
    __half2 v2 = *(__half2*)&vb_; \
    acc[0] = __hfma2(v2, e4m3x2_to_h2((unsigned short)(AA.x & 0xffff)), acc[0]); \
    acc[1] = __hfma2(v2, e4m3x2_to_h2((unsigned short)(AA.x >> 16)), acc[1]); \
    acc[2] = __hfma2(v2, e4m3x2_to_h2((unsigned short)(AA.y & 0xffff)), acc[2]); \
    acc[3] = __hfma2(v2, e4m3x2_to_h2((unsigned short)(AA.y >> 16)), acc[3]); \
    acc[4] = __hfma2(v2, e4m3x2_to_h2((unsigned short)(AA.z & 0xffff)), acc[4]); \
    acc[5] = __hfma2(v2, e4m3x2_to_h2((unsigned short)(AA.z >> 16)), acc[5]); \
    acc[6] = __hfma2(v2, e4m3x2_to_h2((unsigned short)(AA.w & 0xffff)), acc[6]); \
    acc[7] = __hfma2(v2, e4m3x2_to_h2((unsigned short)(AA.w >> 16)), acc[7]); }

// ---------------- zero + pack x ----------------
__global__ void zero_pack_kernel(const float* __restrict__ x) {
    int i = blockIdx.x * blockDim.x + threadIdx.x;
    if (i < NN) {
        g_deg[i] = 0;
        const float* xr = x + (long)i * 5;
        uint4 u;
        *(__half2*)&u.x = __floats2half2_rn(xr[0], xr[1]);
        *(__half2*)&u.y = __floats2half2_rn(xr[2], xr[3]);
        *(__half2*)&u.z = __floats2half2_rn(xr[4], 0.f);
        u.w = 0;
        g_xpack[i] = u;
    }
    if (i < NG * 64) g_pool[i] = 0.f;
}

// ---------------- CSR build ----------------
__global__ void hist_kernel(const int4* __restrict__ rows4) {
    int i = blockIdx.x * blockDim.x + threadIdx.x;
    if (i < NE / 4) {
        int4 r = rows4[i];
        int4 k;
        k.x = atomicAdd(&g_deg[r.x], 1);
        k.y = atomicAdd(&g_deg[r.y], 1);
        k.z = atomicAdd(&g_deg[r.z], 1);
        k.w = atomicAdd(&g_deg[r.w], 1);
        g_rank4[i] = k;
    }
}

// shuffle-based block reduce of padded degrees -> bsum (1 barrier)
__global__ void scanA_kernel() {
    __shared__ int ws[16];
    int t = threadIdx.x;
    int i = blockIdx.x * 512 + t;
    int d = (i < NN) ? ((g_deg[i] + 1) & ~1) : 0;
#pragma unroll
    for (int m = 16; m >= 1; m >>= 1) d += __shfl_xor_sync(0xffffffffu, d, m);
    if ((t & 31) == 0) ws[t >> 5] = d;
    __syncthreads();
    if (t < 32) {
        int v = (t < 16) ? ws[t] : 0;
#pragma unroll
        for (int m = 8; m >= 1; m >>= 1) v += __shfl_xor_sync(0xffffffffu, v, m);
        if (t == 0) g_bsum[blockIdx.x] = v;
    }
}

// shuffle-based scan: base from bsum + in-block exclusive scan -> rowptr; zero pads
__global__ void scanC_kernel() {
    __shared__ int warp_sums[16];
    __shared__ int sbase;
    int t = threadIdx.x;
    int bid = blockIdx.x;
    // base = sum of bsum[0..bid-1] (one warp handles it: NB_SCAN<=512 -> 16/lane)
    if (t < 32) {
        int acc = 0;
        for (int j = t; j < bid; j += 32) acc += g_bsum[j];
#pragma unroll
        for (int m = 16; m >= 1; m >>= 1) acc += __shfl_xor_sync(0xffffffffu, acc, m);
        if (t == 0) sbase = acc;
    }
    int i = bid * 512 + t;
    int d = (i < NN) ? g_deg[i] : 0;
    int dp = (d + 1) & ~1;
    // warp-level inclusive scan of dp
    int lane = t & 31, wid = t >> 5;
    int v = dp;
#pragma unroll
    for (int m = 1; m <= 16; m <<= 1) {
        int u = __shfl_up_sync(0xffffffffu, v, m);
        if (lane >= m) v += u;
    }
    if (lane == 31) warp_sums[wid] = v;
    __syncthreads();
    // scan warp sums (warp 0)
    if (t < 32) {
        int w = (t < 16) ? warp_sums[t] : 0;
#pragma unroll
        for (int m = 1; m <= 16; m <<= 1) {
            int u = __shfl_up_sync(0xffffffffu, w, m);
            if (lane >= m) w += u;
        }
        if (t < 16) warp_sums[t] = w;
    }
    __syncthreads();
    int incl = v + (wid > 0 ? warp_sums[wid - 1] : 0);
    if (i < NN) {
        int p = sbase + incl - dp;
        g_rowptr[i] = p;
        if (d & 1) g_csrcv[p + d] = make_int2(0, 0);   // zero the pad slot
        if (i == NN - 1) g_rowptr[NN] = sbase + incl;
    }
}

// rank-based scatter; val stored pre-packed as half2(v,v)
__global__ void scatter_kernel(const int4* __restrict__ rows4,
                               const int4* __restrict__ cols4,
                               const float4* __restrict__ vals4) {
    int i = blockIdx.x * blockDim.x + threadIdx.x;
    if (i < NE / 4) {
        int4 r = rows4[i];
        int4 c = cols4[i];
        float4 v = vals4[i];
        int4 k = g_rank4[i];
        int p0 = __ldg(&g_rowptr[r.x]) + k.x;
        int p1 = __ldg(&g_rowptr[r.y]) + k.y;
        int p2 = __ldg(&g_rowptr[r.z]) + k.z;
        int p3 = __ldg(&g_rowptr[r.w]) + k.w;
        __half2 h0 = __float2half2_rn(v.x);
        __half2 h1 = __float2half2_rn(v.y);
        __half2 h2 = __float2half2_rn(v.z);
        __half2 h3 = __float2half2_rn(v.w);
        g_csrcv[p0] = make_int2(c.x, *(int*)&h0);
        g_csrcv[p1] = make_int2(c.y, *(int*)&h1);
        g_csrcv[p2] = make_int2(c.z, *(int*)&h2);
        g_csrcv[p3] = make_int2(c.w, *(int*)&h3);
    }
}

// ---------------- layer 1: row-per-thread spmm(x), int4 cv loads, MLP 8 ----------
__global__ void __launch_bounds__(128)
spmm_l1_kernel(const float* __restrict__ W1, const float* __restrict__ b1,
               const int* __restrict__ batch) {
    __shared__ float  W1s[320];
    __shared__ float  bs[64];
    __shared__ __half sp_h[128 * 72];   // fp16 staging, padded stride 72
    __shared__ int    sb[128];
    int tid = threadIdx.x;
    for (int i = tid; i < 320; i += 128) W1s[i] = W1[i];
    if (tid < 64) bs[tid] = b1[tid];
    int base = blockIdx.x * 128;
    {
        int nd = base + tid;
        sb[tid] = batch[nd < NN ? nd : (NN - 1)];
    }
    __syncthreads();
    int row = base + tid;
    float a0 = 0, a1 = 0, a2 = 0, a3 = 0, a4 = 0;
    if (row < NN) {
        const int4* csr4 = (const int4*)g_csrcv;
        int start = g_rowptr[row];
        int np = (g_rowptr[row + 1] - start) >> 1;   // padded pairs (pads = 0)
        int p2 = start >> 1;
        for (; np >= 4; np -= 4, p2 += 4) {
            int4 cvA = __ldcs(&csr4[p2]);
            int4 cvB = __ldcs(&csr4[p2 + 1]);
            int4 cvC = __ldcs(&csr4[p2 + 2]);
            int4 cvD = __ldcs(&csr4[p2 + 3]);
            uint4 x0 = g_xpack[cvA.x];
            uint4 x1 = g_xpack[cvA.z];
            uint4 x2 = g_xpack[cvB.x];
            uint4 x3 = g_xpack[cvB.z];
            uint4 x4 = g_xpack[cvC.x];
            uint4 x5 = g_xpack[cvC.z];
            uint4 x6 = g_xpack[cvD.x];
            uint4 x7 = g_xpack[cvD.z];
            L1_EDGEV(x0, cvA.y)
            L1_EDGEV(x1, cvA.w)
            L1_EDGEV(x2, cvB.y)
            L1_EDGEV(x3, cvB.w)
            L1_EDGEV(x4, cvC.y)
            L1_EDGEV(x5, cvC.w)
            L1_EDGEV(x6, cvD.y)
            L1_EDGEV(x7, cvD.w)
        }
        for (; np > 0; np--, p2++) {
            int4 cvA = __ldcs(&csr4[p2]);
            uint4 x0 = g_xpack[cvA.x];
            uint4 x1 = g_xpack[cvA.z];
            L1_EDGEV(x0, cvA.y)
            L1_EDGEV(x1, cvA.w)
        }
    }
    // epilogue: out = relu(acc @ W1 + b1); stage fp16; pack fp8
    uint2 pk[8];
#pragma unroll
    for (int ob = 0; ob < 8; ob++) {
        float o[8];
#pragma unroll
        for (int j = 0; j < 8; j++) {
            int c = ob * 8 + j;
            float t = bs[c];
            t += a0 * W1s[c];
            t += a1 * W1s[64 + c];
            t += a2 * W1s[128 + c];
            t += a3 * W1s[192 + c];
            t += a4 * W1s[256 + c];
            o[j] = (row < NN) ? fmaxf(t, 0.f) : 0.f;
        }
        uint4 sh;
        __half2 h;
        h = __floats2half2_rn(o[0], o[1]); sh.x = *(unsigned*)&h;
        h = __floats2half2_rn(o[2], o[3]); sh.y = *(unsigned*)&h;
        h = __floats2half2_rn(o[4], o[5]); sh.z = *(unsigned*)&h;
        h = __floats2half2_rn(o[6], o[7]); sh.w = *(unsigned*)&h;
        *(uint4*)&sp_h[tid * 72 + ob * 8] = sh;
        unsigned short s01 = f2_to_e4m3x2(o[1], o[0]);
        unsigned short s23 = f2_to_e4m3x2(o[3], o[2]);
        unsigned short s45 = f2_to_e4m3x2(o[5], o[4]);
        unsigned short s67 = f2_to_e4m3x2(o[7], o[6]);
        pk[ob].x = (unsigned)s01 | ((unsigned)s23 << 16);
        pk[ob].y = (unsigned)s45 | ((unsigned)s67 << 16);
    }
    if (row < NN) {
        uint4* dst = (uint4*)(g_x1f8 + (long)row * 8);
        dst[0] = make_uint4(pk[0].x, pk[0].y, pk[1].x, pk[1].y);
        dst[1] = make_uint4(pk[2].x, pk[2].y, pk[3].x, pk[3].y);
        dst[2] = make_uint4(pk[4].x, pk[4].y, pk[5].x, pk[5].y);
        dst[3] = make_uint4(pk[6].x, pk[6].y, pk[7].x, pk[7].y);
    }
    __syncthreads();
    // parallel pool: 128 threads = 2 row-halves x 64 features
    {
        int half = tid >> 6;
        int fidx = tid & 63;
        int rbeg = half * 64;
        int rend = rbeg + 64;
        int rows_here = NN - base; if (rows_here > 128) rows_here = 128;
        if (rend > rows_here) rend = rows_here;
        if (rbeg < rend) {
            float accum = 0.f;
            int gcur = sb[rbeg];
            for (int nn = rbeg; nn < rend; nn++) {
                int g = sb[nn];
                if (g != gcur) {
                    atomicAdd(&g_pool[gcur * 64 + fidx], accum);
                    gcur = g; accum = 0.f;
                }
                accum += __half2float(sp_h[nn * 72 + fidx]);
            }
            atomicAdd(&g_pool[gcur * 64 + fidx], accum);
        }
    }
}

// ---------------- fused fp8 spmm + linear 64->64 + relu + pool ----------------
// SRC=0: gather g_x1f8, write g_x2f8.  SRC=1: gather g_x2f8, no feature write.
template <int SRC>
__global__ void __launch_bounds__(512)
spmm_lin_kernel(const float* __restrict__ W, const float* __restrict__ b,
                const int* __restrict__ batch) {
    __shared__ float  Ws[64 * 64];      // 16 KB row-major [k][o]
    __shared__ __half ins_h[128 * 72];  // 18 KB fp16 staging
    __shared__ float  bs[64];
    __shared__ int    sb[128];
    int tid = threadIdx.x;
    for (int i = tid; i < 64 * 16; i += 512) ((float4*)Ws)[i] = ((const float4*)W)[i];
    if (tid < 64) bs[tid] = b[tid];
    int base = blockIdx.x * 128;
    if (tid >= 384) {
        int nd = base + (tid - 384);
        sb[tid - 384] = batch[nd < NN ? nd : (NN - 1)];
    }
    // ---- gather phase ----
    {
        int f = tid & 3;
        int r = tid >> 2;
        int row = base + r;
        const uint4* __restrict__ xin = (const uint4*)(SRC == 0 ? g_x1f8 : g_x2f8);
        const int4* csr4 = (const int4*)g_csrcv;
        __half2 acc[8];
#pragma unroll
        for (int j = 0; j < 8; j++) acc[j] = __floats2half2_rn(0.f, 0.f);
        if (row < NN) {
            int start = g_rowptr[row];
            int np = (g_rowptr[row + 1] - start) >> 1;   // padded pairs
            int p2 = start >> 1;
            for (; np >= 2; np -= 2, p2 += 2) {
                int4 cvA = __ldcs(&csr4[p2]);
                int4 cvB = __ldcs(&csr4[p2 + 1]);
                uint4 a0 = xin[(long)cvA.x * 4 + f];
                uint4 a1 = xin[(long)cvA.z * 4 + f];
                uint4 a2 = xin[(long)cvB.x * 4 + f];
                uint4 a3 = xin[(long)cvB.z * 4 + f];
                F8_EDGEV(a0, cvA.y)
                F8_EDGEV(a1, cvA.w)
                F8_EDGEV(a2, cvB.y)
                F8_EDGEV(a3, cvB.w)
            }
            if (np > 0) {
                int4 cvA = __ldcs(&csr4[p2]);
                uint4 a0 = xin[(long)cvA.x * 4 + f];
                uint4 a1 = xin[(long)cvA.z * 4 + f];
                F8_EDGEV(a0, cvA.y)
                F8_EDGEV(a1, cvA.w)
            }
        }
        uint4 u0 = make_uint4(*(unsigned*)&acc[0], *(unsigned*)&acc[1],
                              *(unsigned*)&acc[2], *(unsigned*)&acc[3]);
        uint4 u1 = make_uint4(*(unsigned*)&acc[4], *(unsigned*)&acc[5],
                              *(unsigned*)&acc[6], *(unsigned*)&acc[7]);
        *(uint4*)&ins_h[r * 72 + f * 16 + 0] = u0;
        *(uint4*)&ins_h[r * 72 + f * 16 + 8] = u1;
    }
    __syncthreads();
    // ---- GEMM phase ----
    int p = tid >> 3;
    int q = tid & 7;
    int n0 = 2 * p, n1 = 2 * p + 1;
    unsigned long long a0[4], a1[4];
#pragma unroll
    for (int j = 0; j < 4; j++) {
        unsigned long long bj = pk2(bs[q * 8 + 2 * j], bs[q * 8 + 2 * j + 1]);
        a0[j] = bj; a1[j] = bj;
    }
    const ulonglong2* W64 = (const ulonglong2*)Ws;
#pragma unroll 4
    for (int k = 0; k < 64; k += 2) {
        unsigned xp0 = *(const unsigned*)&ins_h[n0 * 72 + k];
        unsigned xp1 = *(const unsigned*)&ins_h[n1 * 72 + k];
        float2 xf0 = __half22float2(*(__half2*)&xp0);
        float2 xf1 = __half22float2(*(__half2*)&xp1);
        ulonglong2 w0 = W64[k * 8 + q * 2 + 0];
        ulonglong2 w1 = W64[k * 8 + q * 2 + 1];
        ulonglong2 v0 = W64[(k + 1) * 8 + q * 2 + 0];
        ulonglong2 v1 = W64[(k + 1) * 8 + q * 2 + 1];
        unsigned long long x00 = pk2(xf0.x, xf0.x);
        unsigned long long x01 = pk2(xf0.y, xf0.y);
        unsigned long long x10 = pk2(xf1.x, xf1.x);
        unsigned long long x11 = pk2(xf1.y, xf1.y);
        a0[0] = fma2(x00, w0.x, a0[0]);
        a0[1] = fma2(x00, w0.y, a0[1]);
        a0[2] = fma2(x00, w1.x, a0[2]);
        a0[3] = fma2(x00, w1.y, a0[3]);
        a1[0] = fma2(x10, w0.x, a1[0]);
        a1[1] = fma2(x10, w0.y, a1[1]);
        a1[2] = fma2(x10, w1.x, a1[2]);
        a1[3] = fma2(x10, w1.y, a1[3]);
        a0[0] = fma2(x01, v0.x, a0[0]);
        a0[1] = fma2(x01, v0.y, a0[1]);
        a0[2] = fma2(x01, v1.x, a0[2]);
        a0[3] = fma2(x01, v1.y, a0[3]);
        a1[0] = fma2(x11, v0.x, a1[0]);
        a1[1] = fma2(x11, v0.y, a1[1]);
        a1[2] = fma2(x11, v1.x, a1[2]);
        a1[3] = fma2(x11, v1.y, a1[3]);
    }
    float o0[8], o1[8];
#pragma unroll
    for (int j = 0; j < 4; j++) {
        upk2(a0[j], o0[2 * j], o0[2 * j + 1]);
        upk2(a1[j], o1[2 * j], o1[2 * j + 1]);
    }
#pragma unroll
    for (int j = 0; j < 8; j++) { o0[j] = fmaxf(o0[j], 0.f); o1[j] = fmaxf(o1[j], 0.f); }
    int node0 = base + n0, node1 = base + n1;
    if (SRC == 0) {
        if (node0 < NN) {
            uint2 w;
            w.x = (unsigned)f2_to_e4m3x2(o0[1], o0[0]) | ((unsigned)f2_to_e4m3x2(o0[3], o0[2]) << 16);
            w.y = (unsigned)f2_to_e4m3x2(o0[5], o0[4]) | ((unsigned)f2_to_e4m3x2(o0[7], o0[6]) << 16);
            g_x2f8[(long)node0 * 8 + q] = w;
        }
        if (node1 < NN) {
            uint2 w;
            w.x = (unsigned)f2_to_e4m3x2(o1[1], o1[0]) | ((unsigned)f2_to_e4m3x2(o1[3], o1[2]) << 16);
            w.y = (unsigned)f2_to_e4m3x2(o1[5], o1[4]) | ((unsigned)f2_to_e4m3x2(o1[7], o1[6]) << 16);
            g_x2f8[(long)node1 * 8 + q] = w;
        }
    }
    // ---- pool staging (reuse ins_h) ----
    __syncthreads();
    {
        if (node0 >= NN) { o0[0]=o0[1]=o0[2]=o0[3]=o0[4]=o0[5]=o0[6]=o0[7]=0.f; }
        if (node1 >= NN) { o1[0]=o1[1]=o1[2]=o1[3]=o1[4]=o1[5]=o1[6]=o1[7]=0.f; }
        uint4 s0, s1;
        __half2 h;
        h = __floats2half2_rn(o0[0], o0[1]); s0.x = *(unsigned*)&h;
        h = __floats2half2_rn(o0[2], o0[3]); s0.y = *(unsigned*)&h;
        h = __floats2half2_rn(o0[4], o0[5]); s0.z = *(unsigned*)&h;
        h = __floats2half2_rn(o0[6], o0[7]); s0.w = *(unsigned*)&h;
        h = __floats2half2_rn(o1[0], o1[1]); s1.x = *(unsigned*)&h;
        h = __floats2half2_rn(o1[2], o1[3]); s1.y = *(unsigned*)&h;
        h = __floats2half2_rn(o1[4], o1[5]); s1.z = *(unsigned*)&h;
        h = __floats2half2_rn(o1[6], o1[7]); s1.w = *(unsigned*)&h;
        *(uint4*)&ins_h[n0 * 72 + q * 8] = s0;
        *(uint4*)&ins_h[n1 * 72 + q * 8] = s1;
    }
    __syncthreads();
    // parallel pool: 256 threads = 4 row-quarters x 64 features
    if (tid < 256) {
        int quarter = tid >> 6;
        int fidx = tid & 63;
        int rbeg = quarter * 32;
        int rend = rbeg + 32;
        int rows_here = NN - base; if (rows_here > 128) rows_here = 128;
        if (rend > rows_here) rend = rows_here;
        if (rbeg < rend) {
            float accum = 0.f;
            int gcur = sb[rbeg];
            for (int nn = rbeg; nn < rend; nn++) {
                int g = sb[nn];
                if (g != gcur) {
                    atomicAdd(&g_pool[gcur * 64 + fidx], accum);
                    gcur = g; accum = 0.f;
                }
                accum += __half2float(ins_h[nn * 72 + fidx]);
            }
            atomicAdd(&g_pool[gcur * 64 + fidx], accum);
        }
    }
}

// ---------------- final linear 64->10 + softmax ----------------
__global__ void final_kernel(const int* __restrict__ batch,
                             const float* __restrict__ Wl, const float* __restrict__ bl,
                             float* __restrict__ out) {
    __shared__ float Ws[64 * 10];
    __shared__ float bs[10];
    int tid = threadIdx.x;
    for (int i = tid; i < 640; i += 256) Ws[i] = Wl[i];
    if (tid < 10) bs[tid] = bl[tid];
    __syncthreads();
    int g = tid;
    int lo = 0, hi = NN;
    while (lo < hi) { int mid = (lo + hi) >> 1; if (batch[mid] < g) lo = mid + 1; else hi = mid; }
    int lb = lo;
    lo = 0; hi = NN;
    while (lo < hi) { int mid = (lo + hi) >> 1; if (batch[mid] < g + 1) lo = mid + 1; else hi = mid; }
    float cnt = (float)(lo - lb);
    float inv = 1.0f / (3.0f * fmaxf(cnt, 1.0f));
    float logits[10];
#pragma unroll
    for (int o = 0; o < 10; o++) logits[o] = bs[o];
    for (int f = 0; f < 64; f++) {
        float m = g_pool[g * 64 + f] * inv;
#pragma unroll
        for (int o = 0; o < 10; o++) logits[o] += m * Ws[f * 10 + o];
    }
    float mx = logits[0];
#pragma unroll
    for (int o = 1; o < 10; o++) mx = fmaxf(mx, logits[o]);
    float sum = 0.f;
#pragma unroll
    for (int o = 0; o < 10; o++) { logits[o] = expf(logits[o] - mx); sum += logits[o]; }
    float is = 1.0f / sum;
#pragma unroll
    for (int o = 0; o < 10; o++) out[g * 10 + o] = logits[o] * is;
}

// ---------------- launch ----------------
extern "C" void kernel_launch(void* const* d_in, const int* in_sizes, int n_in,
                              void* d_out, int out_size) {
    const float* x    = (const float*)d_in[0];
    const int*   rows = (const int*)d_in[1];
    const int*   cols = (const int*)d_in[2];
    const float* vals = (const float*)d_in[3];
    const int*   batch= (const int*)d_in[4];
    const float* W1 = (const float*)d_in[5];
    const float* b1 = (const float*)d_in[6];
    const float* W2 = (const float*)d_in[7];
    const float* b2 = (const float*)d_in[8];
    const float* W3 = (const float*)d_in[9];
    const float* b3 = (const float*)d_in[10];
    const float* Wl = (const float*)d_in[11];
    const float* bl = (const float*)d_in[12];
    float* out = (float*)d_out;

    zero_pack_kernel<<<(NN + 255) / 256, 256>>>(x);
    hist_kernel<<<(NE / 4 + 255) / 256, 256>>>((const int4*)rows);
    scanA_kernel<<<NB_SCAN, 512>>>();
    scanC_kernel<<<NB_SCAN, 512>>>();
    scatter_kernel<<<(NE / 4 + 255) / 256, 256>>>((const int4*)rows, (const int4*)cols,
                                                  (const float4*)vals);

    spmm_l1_kernel<<<(NN + 127) / 128, 128>>>(W1, b1, batch);      // x1 -> fp8 + pool
    spmm_lin_kernel<0><<<(NN + 127) / 128, 512>>>(W2, b2, batch);  // x2 -> fp8 + pool
    spmm_lin_kernel<1><<<(NN + 127) / 128, 512>>>(W3, b3, batch);  // x3 -> pool

    final_kernel<<<1, 256>>>(batch, Wl, bl, out);
}

// round 17
// speedup vs baseline: 1.5025x; 1.4604x over previous
#include <cuda_runtime.h>
#include <cuda_fp16.h>

#define NN 100000
#define NE 3200000
#define NG 256
#define NB_SCAN 196   // ceil(NN/512)

// ---------------- static scratch ----------------
__device__ int    g_deg[NN];
__device__ int    g_rowptr[NN + 1];      // even-aligned row starts
__device__ int    g_bsum[NB_SCAN];
__device__ int4   g_rank4[NE / 4];       // per-edge rank within its row
__device__ int2   g_csrcv[NE + NN];      // (col, val as half2(v,v)) CSR, rows padded even
__device__ uint4  g_xpack[NN];           // x packed: 5 x fp16 + pad (16B/node)
__device__ uint2  g_x1f8[NN * 8];        // x1 fp8 e4m3 [NN,64]
__device__ uint2  g_x2f8[NN * 8];        // x2 fp8 e4m3 [NN,64]
__device__ float  g_pool[NG * 64];

// ---------------- fp8 helpers ----------------
static __forceinline__ __device__ __half2 e4m3x2_to_h2(unsigned short u) {
    unsigned int r;
    asm("cvt.rn.f16x2.e4m3x2 %0, %1;" : "=r"(r) : "h"(u));
    return *(__half2*)&r;
}
static __forceinline__ __device__ unsigned short f2_to_e4m3x2(float hi, float lo) {
    unsigned short r;
    asm("cvt.rn.satfinite.e4m3x2.f32 %0, %1, %2;" : "=h"(r) : "f"(hi), "f"(lo));
    return r;
}

// edge-accumulate macros (VB = half2(v,v) bits)
#define L1_EDGEV(XA, VB) { \
    unsigned vb_ = (unsigned)(VB); \
    float v = __half2float(*(__half*)&vb_); \
    float2 p01 = __half22float2(*(__half2*)&XA.x); \
    float2 p23 = __half22float2(*(__half2*)&XA.y); \
    float2 p4x = __half22float2(*(__half2*)&XA.z); \
    a0 += v * p01.x; a1 += v * p01.y; a2 += v * p23.x; \
    a3 += v * p23.y; a4 += v * p4x.x; }

#define F8_EDGEV(AA, VB) { \
    unsigned vb_ = (unsigned)(VB); \
    __half2 v2 = *(__half2*)&vb_; \
    acc[0] = __hfma2(v2, e4m3x2_to_h2((unsigned short)(AA.x & 0xffff)), acc[0]); \
    acc[1] = __hfma2(v2, e4m3x2_to_h2((unsigned short)(AA.x >> 16)), acc[1]); \
    acc[2] = __hfma2(v2, e4m3x2_to_h2((unsigned short)(AA.y & 0xffff)), acc[2]); \
    acc[3] = __hfma2(v2, e4m3x2_to_h2((unsigned short)(AA.y >> 16)), acc[3]); \
    acc[4] = __hfma2(v2, e4m3x2_to_h2((unsigned short)(AA.z & 0xffff)), acc[4]); \
    acc[5] = __hfma2(v2, e4m3x2_to_h2((unsigned short)(AA.z >> 16)), acc[5]); \
    acc[6] = __hfma2(v2, e4m3x2_to_h2((unsigned short)(AA.w & 0xffff)), acc[6]); \
    acc[7] = __hfma2(v2, e4m3x2_to_h2((unsigned short)(AA.w >> 16)), acc[7]); }

// ---------------- zero + pack x ----------------
__global__ void zero_pack_kernel(const float* __restrict__ x) {
    int i = blockIdx.x * blockDim.x + threadIdx.x;
    if (i < NN) {
        g_deg[i] = 0;
        const float* xr = x + (long)i * 5;
        uint4 u;
        *(__half2*)&u.x = __floats2half2_rn(xr[0], xr[1]);
        *(__half2*)&u.y = __floats2half2_rn(xr[2], xr[3]);
        *(__half2*)&u.z = __floats2half2_rn(xr[4], 0.f);
        u.w = 0;
        g_xpack[i] = u;
    }
    if (i < NG * 64) g_pool[i] = 0.f;
}

// ---------------- CSR build ----------------
__global__ void hist_kernel(const int4* __restrict__ rows4) {
    int i = blockIdx.x * blockDim.x + threadIdx.x;
    if (i < NE / 4) {
        int4 r = rows4[i];
        int4 k;
        k.x = atomicAdd(&g_deg[r.x], 1);
        k.y = atomicAdd(&g_deg[r.y], 1);
        k.z = atomicAdd(&g_deg[r.z], 1);
        k.w = atomicAdd(&g_deg[r.w], 1);
        g_rank4[i] = k;
    }
}

__global__ void scanA_kernel() {
    __shared__ int ws[16];
    int t = threadIdx.x;
    int i = blockIdx.x * 512 + t;
    int d = (i < NN) ? ((g_deg[i] + 1) & ~1) : 0;
#pragma unroll
    for (int m = 16; m >= 1; m >>= 1) d += __shfl_xor_sync(0xffffffffu, d, m);
    if ((t & 31) == 0) ws[t >> 5] = d;
    __syncthreads();
    if (t < 32) {
        int v = (t < 16) ? ws[t] : 0;
#pragma unroll
        for (int m = 8; m >= 1; m >>= 1) v += __shfl_xor_sync(0xffffffffu, v, m);
        if (t == 0) g_bsum[blockIdx.x] = v;
    }
}

__global__ void scanC_kernel() {
    __shared__ int warp_sums[16];
    __shared__ int sbase;
    int t = threadIdx.x;
    int bid = blockIdx.x;
    if (t < 32) {
        int acc = 0;
        for (int j = t; j < bid; j += 32) acc += g_bsum[j];
#pragma unroll
        for (int m = 16; m >= 1; m >>= 1) acc += __shfl_xor_sync(0xffffffffu, acc, m);
        if (t == 0) sbase = acc;
    }
    int i = bid * 512 + t;
    int d = (i < NN) ? g_deg[i] : 0;
    int dp = (d + 1) & ~1;
    int lane = t & 31, wid = t >> 5;
    int v = dp;
#pragma unroll
    for (int m = 1; m <= 16; m <<= 1) {
        int u = __shfl_up_sync(0xffffffffu, v, m);
        if (lane >= m) v += u;
    }
    if (lane == 31) warp_sums[wid] = v;
    __syncthreads();
    if (t < 32) {
        int w = (t < 16) ? warp_sums[t] : 0;
#pragma unroll
        for (int m = 1; m <= 16; m <<= 1) {
            int u = __shfl_up_sync(0xffffffffu, w, m);
            if (lane >= m) w += u;
        }
        if (t < 16) warp_sums[t] = w;
    }
    __syncthreads();
    int incl = v + (wid > 0 ? warp_sums[wid - 1] : 0);
    if (i < NN) {
        int p = sbase + incl - dp;
        g_rowptr[i] = p;
        if (d & 1) g_csrcv[p + d] = make_int2(0, 0);
        if (i == NN - 1) g_rowptr[NN] = sbase + incl;
    }
}

__global__ void scatter_kernel(const int4* __restrict__ rows4,
                               const int4* __restrict__ cols4,
                               const float4* __restrict__ vals4) {
    int i = blockIdx.x * blockDim.x + threadIdx.x;
    if (i < NE / 4) {
        int4 r = rows4[i];
        int4 c = cols4[i];
        float4 v = vals4[i];
        int4 k = g_rank4[i];
        int p0 = __ldg(&g_rowptr[r.x]) + k.x;
        int p1 = __ldg(&g_rowptr[r.y]) + k.y;
        int p2 = __ldg(&g_rowptr[r.z]) + k.z;
        int p3 = __ldg(&g_rowptr[r.w]) + k.w;
        __half2 h0 = __float2half2_rn(v.x);
        __half2 h1 = __float2half2_rn(v.y);
        __half2 h2 = __float2half2_rn(v.z);
        __half2 h3 = __float2half2_rn(v.w);
        g_csrcv[p0] = make_int2(c.x, *(int*)&h0);
        g_csrcv[p1] = make_int2(c.y, *(int*)&h1);
        g_csrcv[p2] = make_int2(c.z, *(int*)&h2);
        g_csrcv[p3] = make_int2(c.w, *(int*)&h3);
    }
}

// ---------------- layer 1: row-per-thread spmm(x) (unchanged from R16) ----------
__global__ void __launch_bounds__(128)
spmm_l1_kernel(const float* __restrict__ W1, const float* __restrict__ b1,
               const int* __restrict__ batch) {
    __shared__ float  W1s[320];
    __shared__ float  bs[64];
    __shared__ __half sp_h[128 * 72];
    __shared__ int    sb[128];
    int tid = threadIdx.x;
    for (int i = tid; i < 320; i += 128) W1s[i] = W1[i];
    if (tid < 64) bs[tid] = b1[tid];
    int base = blockIdx.x * 128;
    {
        int nd = base + tid;
        sb[tid] = batch[nd < NN ? nd : (NN - 1)];
    }
    __syncthreads();
    int row = base + tid;
    float a0 = 0, a1 = 0, a2 = 0, a3 = 0, a4 = 0;
    if (row < NN) {
        const int4* csr4 = (const int4*)g_csrcv;
        int start = g_rowptr[row];
        int np = (g_rowptr[row + 1] - start) >> 1;
        int p2 = start >> 1;
        for (; np >= 4; np -= 4, p2 += 4) {
            int4 cvA = __ldcs(&csr4[p2]);
            int4 cvB = __ldcs(&csr4[p2 + 1]);
            int4 cvC = __ldcs(&csr4[p2 + 2]);
            int4 cvD = __ldcs(&csr4[p2 + 3]);
            uint4 x0 = g_xpack[cvA.x];
            uint4 x1 = g_xpack[cvA.z];
            uint4 x2 = g_xpack[cvB.x];
            uint4 x3 = g_xpack[cvB.z];
            uint4 x4 = g_xpack[cvC.x];
            uint4 x5 = g_xpack[cvC.z];
            uint4 x6 = g_xpack[cvD.x];
            uint4 x7 = g_xpack[cvD.z];
            L1_EDGEV(x0, cvA.y)
            L1_EDGEV(x1, cvA.w)
            L1_EDGEV(x2, cvB.y)
            L1_EDGEV(x3, cvB.w)
            L1_EDGEV(x4, cvC.y)
            L1_EDGEV(x5, cvC.w)
            L1_EDGEV(x6, cvD.y)
            L1_EDGEV(x7, cvD.w)
        }
        for (; np > 0; np--, p2++) {
            int4 cvA = __ldcs(&csr4[p2]);
            uint4 x0 = g_xpack[cvA.x];
            uint4 x1 = g_xpack[cvA.z];
            L1_EDGEV(x0, cvA.y)
            L1_EDGEV(x1, cvA.w)
        }
    }
    uint2 pk[8];
#pragma unroll
    for (int ob = 0; ob < 8; ob++) {
        float o[8];
#pragma unroll
        for (int j = 0; j < 8; j++) {
            int c = ob * 8 + j;
            float t = bs[c];
            t += a0 * W1s[c];
            t += a1 * W1s[64 + c];
            t += a2 * W1s[128 + c];
            t += a3 * W1s[192 + c];
            t += a4 * W1s[256 + c];
            o[j] = (row < NN) ? fmaxf(t, 0.f) : 0.f;
        }
        uint4 sh;
        __half2 h;
        h = __floats2half2_rn(o[0], o[1]); sh.x = *(unsigned*)&h;
        h = __floats2half2_rn(o[2], o[3]); sh.y = *(unsigned*)&h;
        h = __floats2half2_rn(o[4], o[5]); sh.z = *(unsigned*)&h;
        h = __floats2half2_rn(o[6], o[7]); sh.w = *(unsigned*)&h;
        *(uint4*)&sp_h[tid * 72 + ob * 8] = sh;
        unsigned short s01 = f2_to_e4m3x2(o[1], o[0]);
        unsigned short s23 = f2_to_e4m3x2(o[3], o[2]);
        unsigned short s45 = f2_to_e4m3x2(o[5], o[4]);
        unsigned short s67 = f2_to_e4m3x2(o[7], o[6]);
        pk[ob].x = (unsigned)s01 | ((unsigned)s23 << 16);
        pk[ob].y = (unsigned)s45 | ((unsigned)s67 << 16);
    }
    if (row < NN) {
        uint4* dst = (uint4*)(g_x1f8 + (long)row * 8);
        dst[0] = make_uint4(pk[0].x, pk[0].y, pk[1].x, pk[1].y);
        dst[1] = make_uint4(pk[2].x, pk[2].y, pk[3].x, pk[3].y);
        dst[2] = make_uint4(pk[4].x, pk[4].y, pk[5].x, pk[5].y);
        dst[3] = make_uint4(pk[6].x, pk[6].y, pk[7].x, pk[7].y);
    }
    __syncthreads();
    {
        int half = tid >> 6;
        int fidx = tid & 63;
        int rbeg = half * 64;
        int rend = rbeg + 64;
        int rows_here = NN - base; if (rows_here > 128) rows_here = 128;
        if (rend > rows_here) rend = rows_here;
        if (rbeg < rend) {
            float accum = 0.f;
            int gcur = sb[rbeg];
            for (int nn = rbeg; nn < rend; nn++) {
                int g = sb[nn];
                if (g != gcur) {
                    atomicAdd(&g_pool[gcur * 64 + fidx], accum);
                    gcur = g; accum = 0.f;
                }
                accum += __half2float(sp_h[nn * 72 + fidx]);
            }
            atomicAdd(&g_pool[gcur * 64 + fidx], accum);
        }
    }
}

// ---------------- fused fp8 spmm + tensor-core linear + relu + pool ----------------
// 512 threads, 128 rows/block. Gather unchanged; GEMM via mma.sync.m16n8k16.
// SRC=0: gather g_x1f8, write g_x2f8.  SRC=1: gather g_x2f8, no feature write.
template <int SRC>
__global__ void __launch_bounds__(512)
spmm_lin_kernel(const float* __restrict__ W, const float* __restrict__ b,
                const int* __restrict__ batch) {
    __shared__ __half Ws_h[64 * 72];    // 9 KB fp16 weights [k][n], stride 72
    __shared__ __half ins_h[128 * 72];  // 18 KB fp16 staging
    __shared__ float  bs[64];
    __shared__ int    sb[128];
    int tid = threadIdx.x;
    for (int i = tid; i < 64 * 16; i += 512) {
        float4 wv = ((const float4*)W)[i];
        int idx = i * 4;
        int kk = idx >> 6, nn = idx & 63;
        __half2 h01 = __floats2half2_rn(wv.x, wv.y);
        __half2 h23 = __floats2half2_rn(wv.z, wv.w);
        uint2 u; u.x = *(unsigned*)&h01; u.y = *(unsigned*)&h23;
        *(uint2*)&Ws_h[kk * 72 + nn] = u;
    }
    if (tid < 64) bs[tid] = b[tid];
    int base = blockIdx.x * 128;
    if (tid >= 384) {
        int nd = base + (tid - 384);
        sb[tid - 384] = batch[nd < NN ? nd : (NN - 1)];
    }
    // ---- gather phase (unchanged) ----
    {
        int f = tid & 3;
        int r = tid >> 2;
        int row = base + r;
        const uint4* __restrict__ xin = (const uint4*)(SRC == 0 ? g_x1f8 : g_x2f8);
        const int4* csr4 = (const int4*)g_csrcv;
        __half2 acc[8];
#pragma unroll
        for (int j = 0; j < 8; j++) acc[j] = __floats2half2_rn(0.f, 0.f);
        if (row < NN) {
            int start = g_rowptr[row];
            int np = (g_rowptr[row + 1] - start) >> 1;
            int p2 = start >> 1;
            for (; np >= 2; np -= 2, p2 += 2) {
                int4 cvA = __ldcs(&csr4[p2]);
                int4 cvB = __ldcs(&csr4[p2 + 1]);
                uint4 a0 = xin[(long)cvA.x * 4 + f];
                uint4 a1 = xin[(long)cvA.z * 4 + f];
                uint4 a2 = xin[(long)cvB.x * 4 + f];
                uint4 a3 = xin[(long)cvB.z * 4 + f];
                F8_EDGEV(a0, cvA.y)
                F8_EDGEV(a1, cvA.w)
                F8_EDGEV(a2, cvB.y)
                F8_EDGEV(a3, cvB.w)
            }
            if (np > 0) {
                int4 cvA = __ldcs(&csr4[p2]);
                uint4 a0 = xin[(long)cvA.x * 4 + f];
                uint4 a1 = xin[(long)cvA.z * 4 + f];
                F8_EDGEV(a0, cvA.y)
                F8_EDGEV(a1, cvA.w)
            }
        }
        uint4 u0 = make_uint4(*(unsigned*)&acc[0], *(unsigned*)&acc[1],
                              *(unsigned*)&acc[2], *(unsigned*)&acc[3]);
        uint4 u1 = make_uint4(*(unsigned*)&acc[4], *(unsigned*)&acc[5],
                              *(unsigned*)&acc[6], *(unsigned*)&acc[7]);
        *(uint4*)&ins_h[r * 72 + f * 16 + 0] = u0;
        *(uint4*)&ins_h[r * 72 + f * 16 + 8] = u1;
    }
    __syncthreads();
    // ---- tensor-core GEMM: 16 warps = 8 m-tiles (16 rows) x 2 n-halves (32 cols) ----
    int warp = tid >> 5, lane = tid & 31;
    int wm = (warp & 7) * 16;
    int wn = (warp >> 3) * 32;
    float c[4][4];
#pragma unroll
    for (int nt = 0; nt < 4; nt++) {
        c[nt][0] = 0.f; c[nt][1] = 0.f; c[nt][2] = 0.f; c[nt][3] = 0.f;
    }
#pragma unroll
    for (int k0 = 0; k0 < 64; k0 += 16) {
        unsigned a0, a1, a2, a3;
        int arow = wm + (lane & 15);
        int acol = k0 + ((lane >> 4) << 3);
        unsigned aaddr = (unsigned)__cvta_generic_to_shared(&ins_h[arow * 72 + acol]);
        asm volatile("ldmatrix.sync.aligned.m8n8.x4.shared.b16 {%0,%1,%2,%3}, [%4];"
                     : "=r"(a0), "=r"(a1), "=r"(a2), "=r"(a3) : "r"(aaddr));
        int brow = k0 + (lane & 15);
#pragma unroll
        for (int nt = 0; nt < 4; nt++) {
            unsigned b0, b1;
            unsigned baddr = (unsigned)__cvta_generic_to_shared(
                &Ws_h[brow * 72 + wn + nt * 8]);
            asm volatile("ldmatrix.sync.aligned.m8n8.x2.trans.shared.b16 {%0,%1}, [%2];"
                         : "=r"(b0), "=r"(b1) : "r"(baddr));
            asm volatile("mma.sync.aligned.m16n8k16.row.col.f32.f16.f16.f32 "
                         "{%0,%1,%2,%3},{%4,%5,%6,%7},{%8,%9},{%0,%1,%2,%3};"
                         : "+f"(c[nt][0]), "+f"(c[nt][1]), "+f"(c[nt][2]), "+f"(c[nt][3])
                         : "r"(a0), "r"(a1), "r"(a2), "r"(a3), "r"(b0), "r"(b1));
        }
    }
    // bias + relu + OOB zero
    int row0 = wm + (lane >> 2);
    int row1 = row0 + 8;
    bool ok0 = (base + row0) < NN;
    bool ok1 = (base + row1) < NN;
#pragma unroll
    for (int nt = 0; nt < 4; nt++) {
        int col = wn + nt * 8 + (lane & 3) * 2;
        float bA = bs[col], bB = bs[col + 1];
        c[nt][0] = ok0 ? fmaxf(c[nt][0] + bA, 0.f) : 0.f;
        c[nt][1] = ok0 ? fmaxf(c[nt][1] + bB, 0.f) : 0.f;
        c[nt][2] = ok1 ? fmaxf(c[nt][2] + bA, 0.f) : 0.f;
        c[nt][3] = ok1 ? fmaxf(c[nt][3] + bB, 0.f) : 0.f;
    }
    __syncthreads();   // all ldmatrix A reads of ins_h complete
#pragma unroll
    for (int nt = 0; nt < 4; nt++) {
        int col = wn + nt * 8 + (lane & 3) * 2;
        *(__half2*)&ins_h[row0 * 72 + col] = __floats2half2_rn(c[nt][0], c[nt][1]);
        *(__half2*)&ins_h[row1 * 72 + col] = __floats2half2_rn(c[nt][2], c[nt][3]);
    }
    __syncthreads();
    // ---- fp8 pack pass (coalesced, SRC==0 only) ----
    if (SRC == 0) {
        int r = tid >> 2, f = tid & 3;
        int node = base + r;
        if (node < NN) {
            const __half2* src = (const __half2*)&ins_h[r * 72 + f * 16];
            unsigned short s[8];
#pragma unroll
            for (int j = 0; j < 8; j++) {
                float2 tf = __half22float2(src[j]);
                s[j] = f2_to_e4m3x2(tf.y, tf.x);
            }
            uint2 w0, w1;
            w0.x = (unsigned)s[0] | ((unsigned)s[1] << 16);
            w0.y = (unsigned)s[2] | ((unsigned)s[3] << 16);
            w1.x = (unsigned)s[4] | ((unsigned)s[5] << 16);
            w1.y = (unsigned)s[6] | ((unsigned)s[7] << 16);
            g_x2f8[(long)node * 8 + f * 2 + 0] = w0;
            g_x2f8[(long)node * 8 + f * 2 + 1] = w1;
        }
    }
    // ---- parallel pool: 256 threads = 4 row-quarters x 64 features ----
    if (tid < 256) {
        int quarter = tid >> 6;
        int fidx = tid & 63;
        int rbeg = quarter * 32;
        int rend = rbeg + 32;
        int rows_here = NN - base; if (rows_here > 128) rows_here = 128;
        if (rend > rows_here) rend = rows_here;
        if (rbeg < rend) {
            float accum = 0.f;
            int gcur = sb[rbeg];
            for (int nn = rbeg; nn < rend; nn++) {
                int g = sb[nn];
                if (g != gcur) {
                    atomicAdd(&g_pool[gcur * 64 + fidx], accum);
                    gcur = g; accum = 0.f;
                }
                accum += __half2float(ins_h[nn * 72 + fidx]);
            }
            atomicAdd(&g_pool[gcur * 64 + fidx], accum);
        }
    }
}

// ---------------- final linear 64->10 + softmax ----------------
__global__ void final_kernel(const int* __restrict__ batch,
                             const float* __restrict__ Wl, const float* __restrict__ bl,
                             float* __restrict__ out) {
    __shared__ float Ws[64 * 10];
    __shared__ float bs[10];
    int tid = threadIdx.x;
    for (int i = tid; i < 640; i += 256) Ws[i] = Wl[i];
    if (tid < 10) bs[tid] = bl[tid];
    __syncthreads();
    int g = tid;
    int lo = 0, hi = NN;
    while (lo < hi) { int mid = (lo + hi) >> 1; if (batch[mid] < g) lo = mid + 1; else hi = mid; }
    int lb = lo;
    lo = 0; hi = NN;
    while (lo < hi) { int mid = (lo + hi) >> 1; if (batch[mid] < g + 1) lo = mid + 1; else hi = mid; }
    float cnt = (float)(lo - lb);
    float inv = 1.0f / (3.0f * fmaxf(cnt, 1.0f));
    float logits[10];
#pragma unroll
    for (int o = 0; o < 10; o++) logits[o] = bs[o];
    for (int f = 0; f < 64; f++) {
        float m = g_pool[g * 64 + f] * inv;
#pragma unroll
        for (int o = 0; o < 10; o++) logits[o] += m * Ws[f * 10 + o];
    }
    float mx = logits[0];
#pragma unroll
    for (int o = 1; o < 10; o++) mx = fmaxf(mx, logits[o]);
    float sum = 0.f;
#pragma unroll
    for (int o = 0; o < 10; o++) { logits[o] = expf(logits[o] - mx); sum += logits[o]; }
    float is = 1.0f / sum;
#pragma unroll
    for (int o = 0; o < 10; o++) out[g * 10 + o] = logits[o] * is;
}

// ---------------- launch ----------------
extern "C" void kernel_launch(void* const* d_in, const int* in_sizes, int n_in,
                              void* d_out, int out_size) {
    const float* x    = (const float*)d_in[0];
    const int*   rows = (const int*)d_in[1];
    const int*   cols = (const int*)d_in[2];
    const float* vals = (const float*)d_in[3];
    const int*   batch= (const int*)d_in[4];
    const float* W1 = (const float*)d_in[5];
    const float* b1 = (const float*)d_in[6];
    const float* W2 = (const float*)d_in[7];
    const float* b2 = (const float*)d_in[8];
    const float* W3 = (const float*)d_in[9];
    const float* b3 = (const float*)d_in[10];
    const float* Wl = (const float*)d_in[11];
    const float* bl = (const float*)d_in[12];
    float* out = (float*)d_out;

    zero_pack_kernel<<<(NN + 255) / 256, 256>>>(x);
    hist_kernel<<<(NE / 4 + 255) / 256, 256>>>((const int4*)rows);
    scanA_kernel<<<NB_SCAN, 512>>>();
    scanC_kernel<<<NB_SCAN, 512>>>();
    scatter_kernel<<<(NE / 4 + 255) / 256, 256>>>((const int4*)rows, (const int4*)cols,
                                                  (const float4*)vals);

    spmm_l1_kernel<<<(NN + 127) / 128, 128>>>(W1, b1, batch);      // x1 -> fp8 + pool
    spmm_lin_kernel<0><<<(NN + 127) / 128, 512>>>(W2, b2, batch);  // x2 -> fp8 + pool
    spmm_lin_kernel<1><<<(NN + 127) / 128, 512>>>(W3, b3, batch);  // x3 -> pool

    final_kernel<<<1, 256>>>(batch, Wl, bl, out);
}